// round 1
// baseline (speedup 1.0000x reference)
#include <cuda_runtime.h>
#include <math.h>

// Problem constants
#define BSZ 2
#define SEQ 2048
#define EMB 1024
#define NH  16
#define HD  64

// Scratch (allocation-guard-safe: __device__ globals, bound at module load)
__device__ float g_qkv[(size_t)BSZ * SEQ * 3 * EMB];   // [B, S, 3E]  (50.3 MB)
__device__ float g_attn[(size_t)BSZ * SEQ * EMB];      // [B, S, E]   (16.8 MB)

// ---------------------------------------------------------------------------
// SGEMM:  C[M,N] = A[M,K] @ B[N,K]^T + bias[N]
// BM=BN=64, BK=16, 256 threads, 4x4 micro-tile per thread.
// Smem tiles stored k-major with stride 68 (pad) to keep LDS conflicts <= 2-way.
// ---------------------------------------------------------------------------
__global__ __launch_bounds__(256) void sgemm_bias_kernel(
    const float* __restrict__ A, const float* __restrict__ B,
    const float* __restrict__ bias, float* __restrict__ C,
    int M, int N, int K)
{
    const int BK = 16;
    __shared__ float As[BK][68];
    __shared__ float Bs[BK][68];

    const int tid = threadIdx.x;
    const int tx = tid & 15;        // 0..15 -> N micro
    const int ty = tid >> 4;        // 0..15 -> M micro
    const int m0 = blockIdx.y * 64;
    const int n0 = blockIdx.x * 64;

    const int lr = tid >> 2;        // 0..63 tile row for global loads
    const int lk = (tid & 3) << 2;  // 0,4,8,12 k offset (float4)

    const float* Ag = A + (size_t)(m0 + lr) * K + lk;
    const float* Bg = B + (size_t)(n0 + lr) * K + lk;

    float acc[4][4] = {};

    for (int k0 = 0; k0 < K; k0 += BK) {
        float4 a = *(const float4*)(Ag + k0);
        float4 b = *(const float4*)(Bg + k0);
        __syncthreads();
        As[lk + 0][lr] = a.x; As[lk + 1][lr] = a.y;
        As[lk + 2][lr] = a.z; As[lk + 3][lr] = a.w;
        Bs[lk + 0][lr] = b.x; Bs[lk + 1][lr] = b.y;
        Bs[lk + 2][lr] = b.z; Bs[lk + 3][lr] = b.w;
        __syncthreads();
        #pragma unroll
        for (int kk = 0; kk < BK; ++kk) {
            float4 av = *(const float4*)&As[kk][ty * 4];
            float4 bv = *(const float4*)&Bs[kk][tx * 4];
            acc[0][0] += av.x * bv.x; acc[0][1] += av.x * bv.y;
            acc[0][2] += av.x * bv.z; acc[0][3] += av.x * bv.w;
            acc[1][0] += av.y * bv.x; acc[1][1] += av.y * bv.y;
            acc[1][2] += av.y * bv.z; acc[1][3] += av.y * bv.w;
            acc[2][0] += av.z * bv.x; acc[2][1] += av.z * bv.y;
            acc[2][2] += av.z * bv.z; acc[2][3] += av.z * bv.w;
            acc[3][0] += av.w * bv.x; acc[3][1] += av.w * bv.y;
            acc[3][2] += av.w * bv.z; acc[3][3] += av.w * bv.w;
        }
    }

    const float4 bb = *(const float4*)&bias[n0 + tx * 4];
    #pragma unroll
    for (int i = 0; i < 4; ++i) {
        float4 o;
        o.x = acc[i][0] + bb.x; o.y = acc[i][1] + bb.y;
        o.z = acc[i][2] + bb.z; o.w = acc[i][3] + bb.w;
        *(float4*)&C[(size_t)(m0 + ty * 4 + i) * N + n0 + tx * 4] = o;
    }
}

// ---------------------------------------------------------------------------
// Flash attention, fp32, causal, with the reference's no-transpose head reshape:
// head h of q/k/v is the contiguous block [h*S*D, (h+1)*S*D) of the per-batch
// flattened (S,E) slab. Element f of that slab lives at qkv row f>>10,
// column sel*1024 + (f & 1023).
// One CTA per (qt, h, b): BM=64 q rows, streams BN=64 kv tiles j<=qt.
// 256 threads (16x16), 4x4 per-thread tiles, online softmax.
// Smem: Qs[64][64], KsT[64][68] (k-major, padded), Vs[64][64], Ps[64][64].
// ---------------------------------------------------------------------------
#define FLASH_SMEM ((4096 + 64 * 68 + 4096 + 4096) * 4)

__global__ __launch_bounds__(256) void flash_kernel(
    const float* __restrict__ qkv, float* __restrict__ outp)
{
    extern __shared__ float sm[];
    float* Qs  = sm;                  // [64][64]
    float* KsT = sm + 4096;           // [64][68]  KsT[k][c]
    float* Vs  = KsT + 64 * 68;       // [64][64]  Vs[j][d]
    float* Ps  = Vs + 4096;           // [64][64]  Ps[r][j]

    const int b = blockIdx.z, h = blockIdx.y, qt = blockIdx.x;
    const int tid = threadIdx.x;
    const int tx = tid & 15, ty = tid >> 4;
    const size_t bbase = (size_t)b * SEQ * 3 * EMB;
    const int hbase = h * SEQ * HD;
    const int q0 = qt * 64;

    const int lr16 = tid >> 4;          // 0..15
    const int lc4  = (tid & 15) * 4;    // 0..60

    // Load Q tile [64][64]
    #pragma unroll
    for (int rr = 0; rr < 4; ++rr) {
        const int r = rr * 16 + lr16;
        const int f = hbase + (q0 + r) * HD + lc4;
        const float4 v = *(const float4*)&qkv[bbase + (size_t)(f >> 10) * 3072 + (f & 1023)];
        *(float4*)&Qs[r * 64 + lc4] = v;
    }

    float m_i[4], l_i[4], o[4][4];
    #pragma unroll
    for (int i = 0; i < 4; ++i) {
        m_i[i] = -INFINITY; l_i[i] = 0.f;
        o[i][0] = o[i][1] = o[i][2] = o[i][3] = 0.f;
    }

    for (int j0 = 0; j0 <= qt; ++j0) {
        const int n0 = j0 * 64;
        // Prefetch K,V tiles into registers
        float4 kv4[4], vv4[4];
        #pragma unroll
        for (int rr = 0; rr < 4; ++rr) {
            const int c = rr * 16 + lr16;
            const int fk = hbase + (n0 + c) * HD + lc4;
            const size_t base = bbase + (size_t)(fk >> 10) * 3072 + (fk & 1023);
            kv4[rr] = *(const float4*)&qkv[base + 1024];
            vv4[rr] = *(const float4*)&qkv[base + 2048];
        }
        __syncthreads();   // prior iteration finished reading KsT/Vs/Ps
        #pragma unroll
        for (int rr = 0; rr < 4; ++rr) {
            const int c = rr * 16 + lr16;
            KsT[(lc4 + 0) * 68 + c] = kv4[rr].x;
            KsT[(lc4 + 1) * 68 + c] = kv4[rr].y;
            KsT[(lc4 + 2) * 68 + c] = kv4[rr].z;
            KsT[(lc4 + 3) * 68 + c] = kv4[rr].w;
            *(float4*)&Vs[c * 64 + lc4] = vv4[rr];
        }
        __syncthreads();

        // S = Q @ K^T  (4x4 per thread: rows 4ty+i, cols 4tx+j)
        float s[4][4] = {};
        #pragma unroll 4
        for (int k4 = 0; k4 < 64; k4 += 4) {
            float qreg[4][4];
            #pragma unroll
            for (int i = 0; i < 4; ++i) {
                float4 qv = *(const float4*)&Qs[(ty * 4 + i) * 64 + k4];
                qreg[i][0] = qv.x; qreg[i][1] = qv.y;
                qreg[i][2] = qv.z; qreg[i][3] = qv.w;
            }
            #pragma unroll
            for (int t = 0; t < 4; ++t) {
                const float4 kv = *(const float4*)&KsT[(k4 + t) * 68 + tx * 4];
                #pragma unroll
                for (int i = 0; i < 4; ++i) {
                    s[i][0] += qreg[i][t] * kv.x;
                    s[i][1] += qreg[i][t] * kv.y;
                    s[i][2] += qreg[i][t] * kv.z;
                    s[i][3] += qreg[i][t] * kv.w;
                }
            }
        }

        // scale, causal mask (diagonal tile only), online softmax
        const float scale = 0.125f;   // 1/sqrt(64)
        #pragma unroll
        for (int i = 0; i < 4; ++i) {
            #pragma unroll
            for (int j = 0; j < 4; ++j) s[i][j] *= scale;
            if (j0 == qt) {
                #pragma unroll
                for (int j = 0; j < 4; ++j)
                    if (tx * 4 + j > ty * 4 + i) s[i][j] = -INFINITY;
            }
            float mx = fmaxf(fmaxf(s[i][0], s[i][1]), fmaxf(s[i][2], s[i][3]));
            #pragma unroll
            for (int w = 8; w >= 1; w >>= 1)
                mx = fmaxf(mx, __shfl_xor_sync(0xffffffffu, mx, w));
            const float mnew = fmaxf(m_i[i], mx);
            const float alpha = __expf(m_i[i] - mnew);
            m_i[i] = mnew;
            float rs = 0.f;
            #pragma unroll
            for (int j = 0; j < 4; ++j) { s[i][j] = __expf(s[i][j] - mnew); rs += s[i][j]; }
            #pragma unroll
            for (int w = 8; w >= 1; w >>= 1)
                rs += __shfl_xor_sync(0xffffffffu, rs, w);
            l_i[i] = l_i[i] * alpha + rs;
            o[i][0] *= alpha; o[i][1] *= alpha; o[i][2] *= alpha; o[i][3] *= alpha;
        }

        // P -> smem
        #pragma unroll
        for (int i = 0; i < 4; ++i) {
            float4 pv; pv.x = s[i][0]; pv.y = s[i][1]; pv.z = s[i][2]; pv.w = s[i][3];
            *(float4*)&Ps[(ty * 4 + i) * 64 + tx * 4] = pv;
        }
        __syncthreads();

        // O += P @ V  (O cols = head dims 4tx+j)
        #pragma unroll 4
        for (int j4 = 0; j4 < 64; j4 += 4) {
            float preg[4][4];
            #pragma unroll
            for (int i = 0; i < 4; ++i) {
                float4 p4 = *(const float4*)&Ps[(ty * 4 + i) * 64 + j4];
                preg[i][0] = p4.x; preg[i][1] = p4.y;
                preg[i][2] = p4.z; preg[i][3] = p4.w;
            }
            #pragma unroll
            for (int t = 0; t < 4; ++t) {
                const float4 vv = *(const float4*)&Vs[(j4 + t) * 64 + tx * 4];
                #pragma unroll
                for (int i = 0; i < 4; ++i) {
                    o[i][0] += preg[i][t] * vv.x;
                    o[i][1] += preg[i][t] * vv.y;
                    o[i][2] += preg[i][t] * vv.z;
                    o[i][3] += preg[i][t] * vv.w;
                }
            }
        }
    }

    // Write O / l  ->  g_attn[b, q, h*64 + d]   (this IS the 0,2,1,3 transpose)
    #pragma unroll
    for (int i = 0; i < 4; ++i) {
        const float inv = 1.f / l_i[i];
        const int r = q0 + ty * 4 + i;
        float4 ov;
        ov.x = o[i][0] * inv; ov.y = o[i][1] * inv;
        ov.z = o[i][2] * inv; ov.w = o[i][3] * inv;
        *(float4*)&outp[((size_t)b * SEQ + r) * EMB + h * HD + tx * 4] = ov;
    }
}

// ---------------------------------------------------------------------------
extern "C" void kernel_launch(void* const* d_in, const int* in_sizes, int n_in,
                              void* d_out, int out_size)
{
    const float* x    = (const float*)d_in[0];   // [B,S,E]
    const float* Wqkv = (const float*)d_in[1];   // [3E,E]
    const float* bqkv = (const float*)d_in[2];   // [3E]
    const float* Wout = (const float*)d_in[3];   // [E,E]
    const float* bout = (const float*)d_in[4];   // [E]
    float* out = (float*)d_out;                  // [B,S,E]

    float *qkv_p, *attn_p;
    cudaGetSymbolAddress((void**)&qkv_p, g_qkv);
    cudaGetSymbolAddress((void**)&attn_p, g_attn);

    cudaFuncSetAttribute(flash_kernel,
                         cudaFuncAttributeMaxDynamicSharedMemorySize, FLASH_SMEM);

    // 1) qkv = x @ Wqkv^T + bqkv    M=4096, N=3072, K=1024
    sgemm_bias_kernel<<<dim3(3072 / 64, 4096 / 64), 256>>>(
        x, Wqkv, bqkv, qkv_p, BSZ * SEQ, 3 * EMB, EMB);

    // 2) causal flash attention per (q-tile, head, batch)
    flash_kernel<<<dim3(SEQ / 64, NH, BSZ), 256, FLASH_SMEM>>>(qkv_p, attn_p);

    // 3) out = attn @ Wout^T + bout  M=4096, N=1024, K=1024
    sgemm_bias_kernel<<<dim3(1024 / 64, 4096 / 64), 256>>>(
        attn_p, Wout, bout, out, BSZ * SEQ, EMB, EMB);
}

// round 2
// speedup vs baseline: 1.5424x; 1.5424x over previous
#include <cuda_runtime.h>
#include <cuda_bf16.h>
#include <math.h>
#include <stdint.h>

// Problem constants
#define BSZ 2
#define SEQ 2048
#define EMB 1024
#define NH  16
#define HD  64

// ---------------------------------------------------------------------------
// Scratch (__device__ globals: allocation-guard-safe)
// ---------------------------------------------------------------------------
__device__ float g_qkv[(size_t)BSZ * SEQ * 3 * EMB];   // [B,S,3E] fp32
__device__ float g_attn[(size_t)BSZ * SEQ * EMB];      // [B,S,E]  fp32

__device__ __nv_bfloat16 g_xhi[(size_t)BSZ * SEQ * EMB];
__device__ __nv_bfloat16 g_xlo[(size_t)BSZ * SEQ * EMB];
__device__ __nv_bfloat16 g_w1hi[(size_t)3 * EMB * EMB];
__device__ __nv_bfloat16 g_w1lo[(size_t)3 * EMB * EMB];
__device__ __nv_bfloat16 g_ahi[(size_t)BSZ * SEQ * EMB];
__device__ __nv_bfloat16 g_alo[(size_t)BSZ * SEQ * EMB];
__device__ __nv_bfloat16 g_w2hi[(size_t)EMB * EMB];
__device__ __nv_bfloat16 g_w2lo[(size_t)EMB * EMB];

// ---------------------------------------------------------------------------
// fp32 -> (bf16 hi, bf16 lo) split.  x = hi + lo + O(2^-17 |x|)
// ---------------------------------------------------------------------------
__global__ __launch_bounds__(256) void split_kernel(
    const float4* __restrict__ in, uint2* __restrict__ hi,
    uint2* __restrict__ lo, int n4)
{
    int i = blockIdx.x * blockDim.x + threadIdx.x;
    if (i >= n4) return;
    float4 v = in[i];
    __nv_bfloat16 h0 = __float2bfloat16(v.x), h1 = __float2bfloat16(v.y);
    __nv_bfloat16 h2 = __float2bfloat16(v.z), h3 = __float2bfloat16(v.w);
    __nv_bfloat16 l0 = __float2bfloat16(v.x - __bfloat162float(h0));
    __nv_bfloat16 l1 = __float2bfloat16(v.y - __bfloat162float(h1));
    __nv_bfloat16 l2 = __float2bfloat16(v.z - __bfloat162float(h2));
    __nv_bfloat16 l3 = __float2bfloat16(v.w - __bfloat162float(h3));
    __nv_bfloat162 hA(h0, h1), hB(h2, h3), lA(l0, l1), lB(l2, l3);
    uint2 H, L;
    H.x = *reinterpret_cast<uint32_t*>(&hA); H.y = *reinterpret_cast<uint32_t*>(&hB);
    L.x = *reinterpret_cast<uint32_t*>(&lA); L.y = *reinterpret_cast<uint32_t*>(&lB);
    hi[i] = H; lo[i] = L;
}

// ---------------------------------------------------------------------------
// Tensor-core split-bf16 GEMM:  C[M,N] = A·B^T + bias, A,B pre-split hi/lo.
// C = Ah·Bh^T + Ah·Bl^T + Al·Bh^T (lo·lo dropped, ~2^-16 relative).
// CTA 128x128x32, 8 warps (2m x 4n), warp 64x32, mma.sync m16n8k16 bf16.
// Smem row stride 40 bf16 (80 B): ldmatrix 8-row groups cover all 32 banks.
// ---------------------------------------------------------------------------
#define SAST 40

__device__ __forceinline__ void ldsm4(uint32_t a, uint32_t& r0, uint32_t& r1,
                                      uint32_t& r2, uint32_t& r3)
{
    asm volatile("ldmatrix.sync.aligned.m8n8.x4.shared.b16 {%0,%1,%2,%3}, [%4];\n"
                 : "=r"(r0), "=r"(r1), "=r"(r2), "=r"(r3) : "r"(a));
}

__device__ __forceinline__ void mma16816(float* d, const uint32_t* a, const uint32_t* b)
{
    asm volatile("mma.sync.aligned.m16n8k16.row.col.f32.bf16.bf16.f32 "
                 "{%0,%1,%2,%3}, {%4,%5,%6,%7}, {%8,%9}, {%0,%1,%2,%3};\n"
                 : "+f"(d[0]), "+f"(d[1]), "+f"(d[2]), "+f"(d[3])
                 : "r"(a[0]), "r"(a[1]), "r"(a[2]), "r"(a[3]), "r"(b[0]), "r"(b[1]));
}

__global__ __launch_bounds__(256, 1) void mma_gemm_bias(
    const __nv_bfloat16* __restrict__ Ahi, const __nv_bfloat16* __restrict__ Alo,
    const __nv_bfloat16* __restrict__ Bhi, const __nv_bfloat16* __restrict__ Blo,
    const float* __restrict__ bias, float* __restrict__ C,
    int M, int N, int K)
{
    __shared__ __nv_bfloat16 sAh[128 * SAST], sAl[128 * SAST];
    __shared__ __nv_bfloat16 sBh[128 * SAST], sBl[128 * SAST];

    const int tid = threadIdx.x, lane = tid & 31, wid = tid >> 5;
    const int wm = (wid >> 2) * 64;   // 0,64
    const int wn = (wid & 3) * 32;    // 0..96
    const int m0 = blockIdx.y * 128, n0 = blockIdx.x * 128;

    // global tile loads: thread t -> row t>>1, 16-bf16 chunk (t&1)
    const int lrow = tid >> 1;
    const int lcol = (tid & 1) * 16;
    const __nv_bfloat16* gAh = Ahi + (size_t)(m0 + lrow) * K + lcol;
    const __nv_bfloat16* gAl = Alo + (size_t)(m0 + lrow) * K + lcol;
    const __nv_bfloat16* gBh = Bhi + (size_t)(n0 + lrow) * K + lcol;
    const __nv_bfloat16* gBl = Blo + (size_t)(n0 + lrow) * K + lcol;
    const int so = lrow * SAST + lcol;

    const uint32_t bAh = (uint32_t)__cvta_generic_to_shared(sAh);
    const uint32_t bAl = (uint32_t)__cvta_generic_to_shared(sAl);
    const uint32_t bBh = (uint32_t)__cvta_generic_to_shared(sBh);
    const uint32_t bBl = (uint32_t)__cvta_generic_to_shared(sBl);

    // ldmatrix lane address offsets (bytes)
    const int aoff = ((wm + (lane & 15)) * SAST + (lane >> 4) * 8) * 2;
    const int boff = ((wn + (lane & 7) + ((lane >> 4) & 1) * 8) * SAST
                      + ((lane >> 3) & 1) * 8) * 2;

    float acc[4][4][4];
    #pragma unroll
    for (int i = 0; i < 4; ++i)
        #pragma unroll
        for (int j = 0; j < 4; ++j)
            acc[i][j][0] = acc[i][j][1] = acc[i][j][2] = acc[i][j][3] = 0.f;

    uint4 pAh0 = *(const uint4*)(gAh), pAh1 = *(const uint4*)(gAh + 8);
    uint4 pAl0 = *(const uint4*)(gAl), pAl1 = *(const uint4*)(gAl + 8);
    uint4 pBh0 = *(const uint4*)(gBh), pBh1 = *(const uint4*)(gBh + 8);
    uint4 pBl0 = *(const uint4*)(gBl), pBl1 = *(const uint4*)(gBl + 8);
    *(uint4*)(sAh + so) = pAh0; *(uint4*)(sAh + so + 8) = pAh1;
    *(uint4*)(sAl + so) = pAl0; *(uint4*)(sAl + so + 8) = pAl1;
    *(uint4*)(sBh + so) = pBh0; *(uint4*)(sBh + so + 8) = pBh1;
    *(uint4*)(sBl + so) = pBl0; *(uint4*)(sBl + so + 8) = pBl1;
    __syncthreads();

    for (int k0 = 0; k0 < K; k0 += 32) {
        const bool more = (k0 + 32 < K);
        if (more) {
            pAh0 = *(const uint4*)(gAh + k0 + 32); pAh1 = *(const uint4*)(gAh + k0 + 40);
            pAl0 = *(const uint4*)(gAl + k0 + 32); pAl1 = *(const uint4*)(gAl + k0 + 40);
            pBh0 = *(const uint4*)(gBh + k0 + 32); pBh1 = *(const uint4*)(gBh + k0 + 40);
            pBl0 = *(const uint4*)(gBl + k0 + 32); pBl1 = *(const uint4*)(gBl + k0 + 40);
        }
        #pragma unroll
        for (int ks = 0; ks < 2; ++ks) {
            const int kb = ks * 32;   // 16 bf16 = 32 bytes
            uint32_t ah[4][4], al[4][4], bh[4][2], bl[4][2];
            #pragma unroll
            for (int mi = 0; mi < 4; ++mi) {
                const int mo = mi * 16 * SAST * 2 + kb;
                ldsm4(bAh + aoff + mo, ah[mi][0], ah[mi][1], ah[mi][2], ah[mi][3]);
                ldsm4(bAl + aoff + mo, al[mi][0], al[mi][1], al[mi][2], al[mi][3]);
            }
            #pragma unroll
            for (int nj = 0; nj < 2; ++nj) {
                const int no = nj * 16 * SAST * 2 + kb;
                uint32_t t0, t1, t2, t3;
                ldsm4(bBh + boff + no, t0, t1, t2, t3);
                bh[nj * 2][0] = t0; bh[nj * 2][1] = t1;
                bh[nj * 2 + 1][0] = t2; bh[nj * 2 + 1][1] = t3;
                ldsm4(bBl + boff + no, t0, t1, t2, t3);
                bl[nj * 2][0] = t0; bl[nj * 2][1] = t1;
                bl[nj * 2 + 1][0] = t2; bl[nj * 2 + 1][1] = t3;
            }
            #pragma unroll
            for (int mi = 0; mi < 4; ++mi)
                #pragma unroll
                for (int ni = 0; ni < 4; ++ni) {
                    mma16816(acc[mi][ni], ah[mi], bh[ni]);
                    mma16816(acc[mi][ni], ah[mi], bl[ni]);
                    mma16816(acc[mi][ni], al[mi], bh[ni]);
                }
        }
        __syncthreads();
        if (more) {
            *(uint4*)(sAh + so) = pAh0; *(uint4*)(sAh + so + 8) = pAh1;
            *(uint4*)(sAl + so) = pAl0; *(uint4*)(sAl + so + 8) = pAl1;
            *(uint4*)(sBh + so) = pBh0; *(uint4*)(sBh + so + 8) = pBh1;
            *(uint4*)(sBl + so) = pBl0; *(uint4*)(sBl + so + 8) = pBl1;
            __syncthreads();
        }
    }

    // Epilogue: c0,c1 -> (r, c..c+1); c2,c3 -> (r+8, c..c+1)
    const int rbase = m0 + wm + (lane >> 2);
    const int cbase = n0 + wn + (lane & 3) * 2;
    #pragma unroll
    for (int mi = 0; mi < 4; ++mi) {
        const int r = rbase + mi * 16;
        #pragma unroll
        for (int ni = 0; ni < 4; ++ni) {
            const int c = cbase + ni * 8;
            const float b0 = bias[c], b1 = bias[c + 1];
            float2 o0 = { acc[mi][ni][0] + b0, acc[mi][ni][1] + b1 };
            float2 o1 = { acc[mi][ni][2] + b0, acc[mi][ni][3] + b1 };
            *(float2*)&C[(size_t)r * N + c] = o0;
            *(float2*)&C[(size_t)(r + 8) * N + c] = o1;
        }
    }
}

// ---------------------------------------------------------------------------
// Flash attention (unchanged from R1 — known good, fp32, causal,
// no-transpose head reshape folded into the index math).
// ---------------------------------------------------------------------------
#define FLASH_SMEM ((4096 + 64 * 68 + 4096 + 4096) * 4)

__global__ __launch_bounds__(256) void flash_kernel(
    const float* __restrict__ qkv, float* __restrict__ outp)
{
    extern __shared__ float sm[];
    float* Qs  = sm;                  // [64][64]
    float* KsT = sm + 4096;           // [64][68]
    float* Vs  = KsT + 64 * 68;       // [64][64]
    float* Ps  = Vs + 4096;           // [64][64]

    const int b = blockIdx.z, h = blockIdx.y, qt = blockIdx.x;
    const int tid = threadIdx.x;
    const int tx = tid & 15, ty = tid >> 4;
    const size_t bbase = (size_t)b * SEQ * 3 * EMB;
    const int hbase = h * SEQ * HD;
    const int q0 = qt * 64;

    const int lr16 = tid >> 4;
    const int lc4  = (tid & 15) * 4;

    #pragma unroll
    for (int rr = 0; rr < 4; ++rr) {
        const int r = rr * 16 + lr16;
        const int f = hbase + (q0 + r) * HD + lc4;
        const float4 v = *(const float4*)&qkv[bbase + (size_t)(f >> 10) * 3072 + (f & 1023)];
        *(float4*)&Qs[r * 64 + lc4] = v;
    }

    float m_i[4], l_i[4], o[4][4];
    #pragma unroll
    for (int i = 0; i < 4; ++i) {
        m_i[i] = -INFINITY; l_i[i] = 0.f;
        o[i][0] = o[i][1] = o[i][2] = o[i][3] = 0.f;
    }

    for (int j0 = 0; j0 <= qt; ++j0) {
        const int n0 = j0 * 64;
        float4 kv4[4], vv4[4];
        #pragma unroll
        for (int rr = 0; rr < 4; ++rr) {
            const int c = rr * 16 + lr16;
            const int fk = hbase + (n0 + c) * HD + lc4;
            const size_t base = bbase + (size_t)(fk >> 10) * 3072 + (fk & 1023);
            kv4[rr] = *(const float4*)&qkv[base + 1024];
            vv4[rr] = *(const float4*)&qkv[base + 2048];
        }
        __syncthreads();
        #pragma unroll
        for (int rr = 0; rr < 4; ++rr) {
            const int c = rr * 16 + lr16;
            KsT[(lc4 + 0) * 68 + c] = kv4[rr].x;
            KsT[(lc4 + 1) * 68 + c] = kv4[rr].y;
            KsT[(lc4 + 2) * 68 + c] = kv4[rr].z;
            KsT[(lc4 + 3) * 68 + c] = kv4[rr].w;
            *(float4*)&Vs[c * 64 + lc4] = vv4[rr];
        }
        __syncthreads();

        float s[4][4] = {};
        #pragma unroll 4
        for (int k4 = 0; k4 < 64; k4 += 4) {
            float qreg[4][4];
            #pragma unroll
            for (int i = 0; i < 4; ++i) {
                float4 qv = *(const float4*)&Qs[(ty * 4 + i) * 64 + k4];
                qreg[i][0] = qv.x; qreg[i][1] = qv.y;
                qreg[i][2] = qv.z; qreg[i][3] = qv.w;
            }
            #pragma unroll
            for (int t = 0; t < 4; ++t) {
                const float4 kv = *(const float4*)&KsT[(k4 + t) * 68 + tx * 4];
                #pragma unroll
                for (int i = 0; i < 4; ++i) {
                    s[i][0] += qreg[i][t] * kv.x;
                    s[i][1] += qreg[i][t] * kv.y;
                    s[i][2] += qreg[i][t] * kv.z;
                    s[i][3] += qreg[i][t] * kv.w;
                }
            }
        }

        const float scale = 0.125f;
        #pragma unroll
        for (int i = 0; i < 4; ++i) {
            #pragma unroll
            for (int j = 0; j < 4; ++j) s[i][j] *= scale;
            if (j0 == qt) {
                #pragma unroll
                for (int j = 0; j < 4; ++j)
                    if (tx * 4 + j > ty * 4 + i) s[i][j] = -INFINITY;
            }
            float mx = fmaxf(fmaxf(s[i][0], s[i][1]), fmaxf(s[i][2], s[i][3]));
            #pragma unroll
            for (int w = 8; w >= 1; w >>= 1)
                mx = fmaxf(mx, __shfl_xor_sync(0xffffffffu, mx, w));
            const float mnew = fmaxf(m_i[i], mx);
            const float alpha = __expf(m_i[i] - mnew);
            m_i[i] = mnew;
            float rs = 0.f;
            #pragma unroll
            for (int j = 0; j < 4; ++j) { s[i][j] = __expf(s[i][j] - mnew); rs += s[i][j]; }
            #pragma unroll
            for (int w = 8; w >= 1; w >>= 1)
                rs += __shfl_xor_sync(0xffffffffu, rs, w);
            l_i[i] = l_i[i] * alpha + rs;
            o[i][0] *= alpha; o[i][1] *= alpha; o[i][2] *= alpha; o[i][3] *= alpha;
        }

        #pragma unroll
        for (int i = 0; i < 4; ++i) {
            float4 pv; pv.x = s[i][0]; pv.y = s[i][1]; pv.z = s[i][2]; pv.w = s[i][3];
            *(float4*)&Ps[(ty * 4 + i) * 64 + tx * 4] = pv;
        }
        __syncthreads();

        #pragma unroll 4
        for (int j4 = 0; j4 < 64; j4 += 4) {
            float preg[4][4];
            #pragma unroll
            for (int i = 0; i < 4; ++i) {
                float4 p4 = *(const float4*)&Ps[(ty * 4 + i) * 64 + j4];
                preg[i][0] = p4.x; preg[i][1] = p4.y;
                preg[i][2] = p4.z; preg[i][3] = p4.w;
            }
            #pragma unroll
            for (int t = 0; t < 4; ++t) {
                const float4 vv = *(const float4*)&Vs[(j4 + t) * 64 + tx * 4];
                #pragma unroll
                for (int i = 0; i < 4; ++i) {
                    o[i][0] += preg[i][t] * vv.x;
                    o[i][1] += preg[i][t] * vv.y;
                    o[i][2] += preg[i][t] * vv.z;
                    o[i][3] += preg[i][t] * vv.w;
                }
            }
        }
    }

    #pragma unroll
    for (int i = 0; i < 4; ++i) {
        const float inv = 1.f / l_i[i];
        const int r = q0 + ty * 4 + i;
        float4 ov;
        ov.x = o[i][0] * inv; ov.y = o[i][1] * inv;
        ov.z = o[i][2] * inv; ov.w = o[i][3] * inv;
        *(float4*)&outp[((size_t)b * SEQ + r) * EMB + h * HD + tx * 4] = ov;
    }
}

// ---------------------------------------------------------------------------
extern "C" void kernel_launch(void* const* d_in, const int* in_sizes, int n_in,
                              void* d_out, int out_size)
{
    const float* x    = (const float*)d_in[0];
    const float* Wqkv = (const float*)d_in[1];
    const float* bqkv = (const float*)d_in[2];
    const float* Wout = (const float*)d_in[3];
    const float* bout = (const float*)d_in[4];
    float* out = (float*)d_out;

    float *qkv_p, *attn_p;
    __nv_bfloat16 *xhi, *xlo, *w1hi, *w1lo, *ahi, *alo, *w2hi, *w2lo;
    cudaGetSymbolAddress((void**)&qkv_p, g_qkv);
    cudaGetSymbolAddress((void**)&attn_p, g_attn);
    cudaGetSymbolAddress((void**)&xhi, g_xhi);
    cudaGetSymbolAddress((void**)&xlo, g_xlo);
    cudaGetSymbolAddress((void**)&w1hi, g_w1hi);
    cudaGetSymbolAddress((void**)&w1lo, g_w1lo);
    cudaGetSymbolAddress((void**)&ahi, g_ahi);
    cudaGetSymbolAddress((void**)&alo, g_alo);
    cudaGetSymbolAddress((void**)&w2hi, g_w2hi);
    cudaGetSymbolAddress((void**)&w2lo, g_w2lo);

    cudaFuncSetAttribute(flash_kernel,
                         cudaFuncAttributeMaxDynamicSharedMemorySize, FLASH_SMEM);

    const int nx  = BSZ * SEQ * EMB;       // 4,194,304
    const int nw1 = 3 * EMB * EMB;         // 3,145,728
    const int nw2 = EMB * EMB;             // 1,048,576

    // 0) fp32 -> hi/lo splits
    split_kernel<<<nx / 4 / 256, 256>>>((const float4*)x, (uint2*)xhi, (uint2*)xlo, nx / 4);
    split_kernel<<<nw1 / 4 / 256, 256>>>((const float4*)Wqkv, (uint2*)w1hi, (uint2*)w1lo, nw1 / 4);
    split_kernel<<<nw2 / 4 / 256, 256>>>((const float4*)Wout, (uint2*)w2hi, (uint2*)w2lo, nw2 / 4);

    // 1) qkv = x @ Wqkv^T + bqkv   (tensor cores, split-bf16)
    mma_gemm_bias<<<dim3(3 * EMB / 128, BSZ * SEQ / 128), 256>>>(
        xhi, xlo, w1hi, w1lo, bqkv, qkv_p, BSZ * SEQ, 3 * EMB, EMB);

    // 2) causal flash attention
    flash_kernel<<<dim3(SEQ / 64, NH, BSZ), 256, FLASH_SMEM>>>(qkv_p, attn_p);

    // 3) split attn output, then out = attn @ Wout^T + bout
    split_kernel<<<nx / 4 / 256, 256>>>((const float4*)attn_p, (uint2*)ahi, (uint2*)alo, nx / 4);
    mma_gemm_bias<<<dim3(EMB / 128, BSZ * SEQ / 128), 256>>>(
        ahi, alo, w2hi, w2lo, bout, out, BSZ * SEQ, EMB, EMB);
}

// round 3
// speedup vs baseline: 2.6334x; 1.7074x over previous
#include <cuda_runtime.h>
#include <cuda_bf16.h>
#include <math.h>
#include <stdint.h>

#define BSZ 2
#define SEQ 2048
#define EMB 1024
#define NH  16
#define HD  64

// ---------------------------------------------------------------------------
// Scratch (__device__ globals)
// ---------------------------------------------------------------------------
__device__ __nv_bfloat16 g_xhi[(size_t)BSZ * SEQ * EMB];
__device__ __nv_bfloat16 g_xlo[(size_t)BSZ * SEQ * EMB];
__device__ __nv_bfloat16 g_w1hi[(size_t)3 * EMB * EMB];
__device__ __nv_bfloat16 g_w1lo[(size_t)3 * EMB * EMB];
__device__ __nv_bfloat16 g_w2hi[(size_t)EMB * EMB];
__device__ __nv_bfloat16 g_w2lo[(size_t)EMB * EMB];
__device__ __nv_bfloat16 g_qkvh[(size_t)BSZ * SEQ * 3 * EMB];
__device__ __nv_bfloat16 g_qkvl[(size_t)BSZ * SEQ * 3 * EMB];
__device__ __nv_bfloat16 g_ahi[(size_t)BSZ * SEQ * EMB];
__device__ __nv_bfloat16 g_alo[(size_t)BSZ * SEQ * EMB];

// ---------------------------------------------------------------------------
// fp32 -> (bf16 hi, bf16 lo)
// ---------------------------------------------------------------------------
__global__ __launch_bounds__(256) void split_kernel(
    const float4* __restrict__ in, uint2* __restrict__ hi,
    uint2* __restrict__ lo, int n4)
{
    int i = blockIdx.x * blockDim.x + threadIdx.x;
    if (i >= n4) return;
    float4 v = in[i];
    __nv_bfloat16 h0 = __float2bfloat16(v.x), h1 = __float2bfloat16(v.y);
    __nv_bfloat16 h2 = __float2bfloat16(v.z), h3 = __float2bfloat16(v.w);
    __nv_bfloat16 l0 = __float2bfloat16(v.x - __bfloat162float(h0));
    __nv_bfloat16 l1 = __float2bfloat16(v.y - __bfloat162float(h1));
    __nv_bfloat16 l2 = __float2bfloat16(v.z - __bfloat162float(h2));
    __nv_bfloat16 l3 = __float2bfloat16(v.w - __bfloat162float(h3));
    __nv_bfloat162 hA(h0, h1), hB(h2, h3), lA(l0, l1), lB(l2, l3);
    uint2 H, L;
    H.x = *reinterpret_cast<uint32_t*>(&hA); H.y = *reinterpret_cast<uint32_t*>(&hB);
    L.x = *reinterpret_cast<uint32_t*>(&lA); L.y = *reinterpret_cast<uint32_t*>(&lB);
    hi[i] = H; lo[i] = L;
}

// ---------------------------------------------------------------------------
// MMA helpers
// ---------------------------------------------------------------------------
__device__ __forceinline__ void ldsm4(uint32_t a, uint32_t& r0, uint32_t& r1,
                                      uint32_t& r2, uint32_t& r3)
{
    asm volatile("ldmatrix.sync.aligned.m8n8.x4.shared.b16 {%0,%1,%2,%3}, [%4];\n"
                 : "=r"(r0), "=r"(r1), "=r"(r2), "=r"(r3) : "r"(a));
}
__device__ __forceinline__ void ldsm4t(uint32_t a, uint32_t& r0, uint32_t& r1,
                                       uint32_t& r2, uint32_t& r3)
{
    asm volatile("ldmatrix.sync.aligned.m8n8.x4.trans.shared.b16 {%0,%1,%2,%3}, [%4];\n"
                 : "=r"(r0), "=r"(r1), "=r"(r2), "=r"(r3) : "r"(a));
}
__device__ __forceinline__ void mma16816(float* d, const uint32_t* a, const uint32_t* b)
{
    asm volatile("mma.sync.aligned.m16n8k16.row.col.f32.bf16.bf16.f32 "
                 "{%0,%1,%2,%3}, {%4,%5,%6,%7}, {%8,%9}, {%0,%1,%2,%3};\n"
                 : "+f"(d[0]), "+f"(d[1]), "+f"(d[2]), "+f"(d[3])
                 : "r"(a[0]), "r"(a[1]), "r"(a[2]), "r"(a[3]), "r"(b[0]), "r"(b[1]));
}
__device__ __forceinline__ uint32_t pack_hi(float a, float b)
{
    __nv_bfloat162 p(__float2bfloat16(a), __float2bfloat16(b));
    return *reinterpret_cast<uint32_t*>(&p);
}
__device__ __forceinline__ uint32_t pack_lo(float a, float b)
{
    __nv_bfloat16 ha = __float2bfloat16(a), hb = __float2bfloat16(b);
    __nv_bfloat162 p(__float2bfloat16(a - __bfloat162float(ha)),
                     __float2bfloat16(b - __bfloat162float(hb)));
    return *reinterpret_cast<uint32_t*>(&p);
}

// ---------------------------------------------------------------------------
// Split-bf16 GEMM: C = A·B^T + bias.  SPLIT_OUT: C emitted as bf16 hi/lo pair
// arrays instead of fp32.  (Same proven R2 structure.)
// ---------------------------------------------------------------------------
#define SAST 40

template<bool SPLIT_OUT>
__global__ __launch_bounds__(256, 1) void mma_gemm_bias(
    const __nv_bfloat16* __restrict__ Ahi, const __nv_bfloat16* __restrict__ Alo,
    const __nv_bfloat16* __restrict__ Bhi, const __nv_bfloat16* __restrict__ Blo,
    const float* __restrict__ bias, float* __restrict__ Cf,
    __nv_bfloat16* __restrict__ Chi, __nv_bfloat16* __restrict__ Clo,
    int M, int N, int K)
{
    __shared__ __nv_bfloat16 sAh[128 * SAST], sAl[128 * SAST];
    __shared__ __nv_bfloat16 sBh[128 * SAST], sBl[128 * SAST];

    const int tid = threadIdx.x, lane = tid & 31, wid = tid >> 5;
    const int wm = (wid >> 2) * 64;
    const int wn = (wid & 3) * 32;
    const int m0 = blockIdx.y * 128, n0 = blockIdx.x * 128;

    const int lrow = tid >> 1;
    const int lcol = (tid & 1) * 16;
    const __nv_bfloat16* gAh = Ahi + (size_t)(m0 + lrow) * K + lcol;
    const __nv_bfloat16* gAl = Alo + (size_t)(m0 + lrow) * K + lcol;
    const __nv_bfloat16* gBh = Bhi + (size_t)(n0 + lrow) * K + lcol;
    const __nv_bfloat16* gBl = Blo + (size_t)(n0 + lrow) * K + lcol;
    const int so = lrow * SAST + lcol;

    const uint32_t bAh = (uint32_t)__cvta_generic_to_shared(sAh);
    const uint32_t bAl = (uint32_t)__cvta_generic_to_shared(sAl);
    const uint32_t bBh = (uint32_t)__cvta_generic_to_shared(sBh);
    const uint32_t bBl = (uint32_t)__cvta_generic_to_shared(sBl);

    const int aoff = ((wm + (lane & 15)) * SAST + (lane >> 4) * 8) * 2;
    const int boff = ((wn + (lane & 7) + ((lane >> 4) & 1) * 8) * SAST
                      + ((lane >> 3) & 1) * 8) * 2;

    float acc[4][4][4];
    #pragma unroll
    for (int i = 0; i < 4; ++i)
        #pragma unroll
        for (int j = 0; j < 4; ++j)
            acc[i][j][0] = acc[i][j][1] = acc[i][j][2] = acc[i][j][3] = 0.f;

    uint4 pAh0 = *(const uint4*)(gAh), pAh1 = *(const uint4*)(gAh + 8);
    uint4 pAl0 = *(const uint4*)(gAl), pAl1 = *(const uint4*)(gAl + 8);
    uint4 pBh0 = *(const uint4*)(gBh), pBh1 = *(const uint4*)(gBh + 8);
    uint4 pBl0 = *(const uint4*)(gBl), pBl1 = *(const uint4*)(gBl + 8);
    *(uint4*)(sAh + so) = pAh0; *(uint4*)(sAh + so + 8) = pAh1;
    *(uint4*)(sAl + so) = pAl0; *(uint4*)(sAl + so + 8) = pAl1;
    *(uint4*)(sBh + so) = pBh0; *(uint4*)(sBh + so + 8) = pBh1;
    *(uint4*)(sBl + so) = pBl0; *(uint4*)(sBl + so + 8) = pBl1;
    __syncthreads();

    for (int k0 = 0; k0 < K; k0 += 32) {
        const bool more = (k0 + 32 < K);
        if (more) {
            pAh0 = *(const uint4*)(gAh + k0 + 32); pAh1 = *(const uint4*)(gAh + k0 + 40);
            pAl0 = *(const uint4*)(gAl + k0 + 32); pAl1 = *(const uint4*)(gAl + k0 + 40);
            pBh0 = *(const uint4*)(gBh + k0 + 32); pBh1 = *(const uint4*)(gBh + k0 + 40);
            pBl0 = *(const uint4*)(gBl + k0 + 32); pBl1 = *(const uint4*)(gBl + k0 + 40);
        }
        #pragma unroll
        for (int ks = 0; ks < 2; ++ks) {
            const int kb = ks * 32;
            uint32_t ah[4][4], al[4][4], bh[4][2], bl[4][2];
            #pragma unroll
            for (int mi = 0; mi < 4; ++mi) {
                const int mo = mi * 16 * SAST * 2 + kb;
                ldsm4(bAh + aoff + mo, ah[mi][0], ah[mi][1], ah[mi][2], ah[mi][3]);
                ldsm4(bAl + aoff + mo, al[mi][0], al[mi][1], al[mi][2], al[mi][3]);
            }
            #pragma unroll
            for (int nj = 0; nj < 2; ++nj) {
                const int no = nj * 16 * SAST * 2 + kb;
                uint32_t t0, t1, t2, t3;
                ldsm4(bBh + boff + no, t0, t1, t2, t3);
                bh[nj * 2][0] = t0; bh[nj * 2][1] = t1;
                bh[nj * 2 + 1][0] = t2; bh[nj * 2 + 1][1] = t3;
                ldsm4(bBl + boff + no, t0, t1, t2, t3);
                bl[nj * 2][0] = t0; bl[nj * 2][1] = t1;
                bl[nj * 2 + 1][0] = t2; bl[nj * 2 + 1][1] = t3;
            }
            #pragma unroll
            for (int mi = 0; mi < 4; ++mi)
                #pragma unroll
                for (int ni = 0; ni < 4; ++ni) {
                    mma16816(acc[mi][ni], ah[mi], bh[ni]);
                    mma16816(acc[mi][ni], ah[mi], bl[ni]);
                    mma16816(acc[mi][ni], al[mi], bh[ni]);
                }
        }
        __syncthreads();
        if (more) {
            *(uint4*)(sAh + so) = pAh0; *(uint4*)(sAh + so + 8) = pAh1;
            *(uint4*)(sAl + so) = pAl0; *(uint4*)(sAl + so + 8) = pAl1;
            *(uint4*)(sBh + so) = pBh0; *(uint4*)(sBh + so + 8) = pBh1;
            *(uint4*)(sBl + so) = pBl0; *(uint4*)(sBl + so + 8) = pBl1;
            __syncthreads();
        }
    }

    const int rbase = m0 + wm + (lane >> 2);
    const int cbase = n0 + wn + (lane & 3) * 2;
    #pragma unroll
    for (int mi = 0; mi < 4; ++mi) {
        const int r = rbase + mi * 16;
        #pragma unroll
        for (int ni = 0; ni < 4; ++ni) {
            const int c = cbase + ni * 8;
            const float b0 = bias[c], b1 = bias[c + 1];
            const float v0 = acc[mi][ni][0] + b0, v1 = acc[mi][ni][1] + b1;
            const float v2 = acc[mi][ni][2] + b0, v3 = acc[mi][ni][3] + b1;
            if (SPLIT_OUT) {
                *(uint32_t*)&Chi[(size_t)r * N + c]       = pack_hi(v0, v1);
                *(uint32_t*)&Clo[(size_t)r * N + c]       = pack_lo(v0, v1);
                *(uint32_t*)&Chi[(size_t)(r + 8) * N + c] = pack_hi(v2, v3);
                *(uint32_t*)&Clo[(size_t)(r + 8) * N + c] = pack_lo(v2, v3);
            } else {
                float2 o0 = { v0, v1 }, o1 = { v2, v3 };
                *(float2*)&Cf[(size_t)r * N + c] = o0;
                *(float2*)&Cf[(size_t)(r + 8) * N + c] = o1;
            }
        }
    }
}

// ---------------------------------------------------------------------------
// Tensor-core flash attention (split-bf16, causal, no-transpose head reshape).
// CTA: 64 q-rows, 4 warps (warp = 16 rows, all 64 cols). KV tiles of 64.
// S = Qh·Kh + Qh·Kl + Ql·Kh;  O += Ph·Vh + Ph·Vl + Pl·Vh.
// Smem rows stride 72 bf16 -> conflict-free ldmatrix (trans & non-trans).
// ---------------------------------------------------------------------------
#define FST 72
#define FLASH_SMEM (6 * 64 * FST * 2)

__global__ __launch_bounds__(128) void flash_mma(
    const __nv_bfloat16* __restrict__ qkvh,
    const __nv_bfloat16* __restrict__ qkvl,
    __nv_bfloat16* __restrict__ ahi, __nv_bfloat16* __restrict__ alo)
{
    extern __shared__ __nv_bfloat16 fsm[];
    __nv_bfloat16* sQh = fsm;
    __nv_bfloat16* sQl = fsm + 64 * FST;
    __nv_bfloat16* sKh = fsm + 2 * 64 * FST;
    __nv_bfloat16* sKl = fsm + 3 * 64 * FST;
    __nv_bfloat16* sVh = fsm + 4 * 64 * FST;
    __nv_bfloat16* sVl = fsm + 5 * 64 * FST;

    const int b = blockIdx.z, h = blockIdx.y, qt = blockIdx.x;
    const int tid = threadIdx.x, lane = tid & 31, wid = tid >> 5;
    const size_t bbase = (size_t)b * SEQ * 3 * EMB;
    const int hbase = h * SEQ * HD;
    const int q0 = qt * 64;

    // ---- stage Q (64x64 hi/lo) ----
    #pragma unroll
    for (int i = 0; i < 4; ++i) {
        const int id = tid + 128 * i;
        const int r = id >> 3, c = (id & 7) * 8;
        const int f = hbase + (q0 + r) * HD + c;
        const size_t ga = bbase + (size_t)(f >> 10) * 3072 + (f & 1023);
        *(uint4*)&sQh[r * FST + c] = *(const uint4*)&qkvh[ga];
        *(uint4*)&sQl[r * FST + c] = *(const uint4*)&qkvl[ga];
    }
    __syncthreads();

    const uint32_t bQh = (uint32_t)__cvta_generic_to_shared(sQh);
    const uint32_t bQl = (uint32_t)__cvta_generic_to_shared(sQl);
    const uint32_t bKh = (uint32_t)__cvta_generic_to_shared(sKh);
    const uint32_t bKl = (uint32_t)__cvta_generic_to_shared(sKl);
    const uint32_t bVh = (uint32_t)__cvta_generic_to_shared(sVh);
    const uint32_t bVl = (uint32_t)__cvta_generic_to_shared(sVl);

    // Q A-fragments cached in registers for the whole KV sweep
    const int aoff = ((wid * 16 + (lane & 15)) * FST + (lane >> 4) * 8) * 2;
    uint32_t qfh[4][4], qfl[4][4];
    #pragma unroll
    for (int kt = 0; kt < 4; ++kt) {
        ldsm4(bQh + aoff + kt * 32, qfh[kt][0], qfh[kt][1], qfh[kt][2], qfh[kt][3]);
        ldsm4(bQl + aoff + kt * 32, qfl[kt][0], qfl[kt][1], qfl[kt][2], qfl[kt][3]);
    }

    const int boffK = (((lane & 7) + ((lane >> 4) & 1) * 8) * FST + ((lane >> 3) & 1) * 8) * 2;
    const int voffV = (((lane & 7) + ((lane >> 3) & 1) * 8) * FST + (lane >> 4) * 8) * 2;

    float m_r[2] = { -INFINITY, -INFINITY };
    float l_r[2] = { 0.f, 0.f };
    float oacc[8][4];
    #pragma unroll
    for (int nt = 0; nt < 8; ++nt)
        oacc[nt][0] = oacc[nt][1] = oacc[nt][2] = oacc[nt][3] = 0.f;

    const int rloc = wid * 16 + (lane >> 2);   // row within q-tile (and +8)
    const int cloc = 2 * (lane & 3);           // col within n8 tile

    for (int j0 = 0; j0 <= qt; ++j0) {
        __syncthreads();   // previous iteration done with K/V smem
        #pragma unroll
        for (int i = 0; i < 4; ++i) {
            const int id = tid + 128 * i;
            const int r = id >> 3, c = (id & 7) * 8;
            const int f = hbase + (j0 * 64 + r) * HD + c;
            const size_t ga = bbase + (size_t)(f >> 10) * 3072 + (f & 1023);
            *(uint4*)&sKh[r * FST + c] = *(const uint4*)&qkvh[ga + 1024];
            *(uint4*)&sKl[r * FST + c] = *(const uint4*)&qkvl[ga + 1024];
            *(uint4*)&sVh[r * FST + c] = *(const uint4*)&qkvh[ga + 2048];
            *(uint4*)&sVl[r * FST + c] = *(const uint4*)&qkvl[ga + 2048];
        }
        __syncthreads();

        // ---- S = Q K^T (split 3-term) ----
        float sacc[8][4];
        #pragma unroll
        for (int nt = 0; nt < 8; ++nt)
            sacc[nt][0] = sacc[nt][1] = sacc[nt][2] = sacc[nt][3] = 0.f;

        #pragma unroll
        for (int kt = 0; kt < 4; ++kt) {
            #pragma unroll
            for (int nj = 0; nj < 4; ++nj) {
                uint32_t h0, h1, h2, h3, l0, l1, l2, l3;
                const int off = nj * 16 * FST * 2 + kt * 32;
                ldsm4(bKh + boffK + off, h0, h1, h2, h3);
                ldsm4(bKl + boffK + off, l0, l1, l2, l3);
                uint32_t bh0[2] = { h0, h1 }, bh1[2] = { h2, h3 };
                uint32_t bl0[2] = { l0, l1 }, bl1[2] = { l2, l3 };
                mma16816(sacc[nj * 2], qfh[kt], bh0);
                mma16816(sacc[nj * 2], qfh[kt], bl0);
                mma16816(sacc[nj * 2], qfl[kt], bh0);
                mma16816(sacc[nj * 2 + 1], qfh[kt], bh1);
                mma16816(sacc[nj * 2 + 1], qfh[kt], bl1);
                mma16816(sacc[nj * 2 + 1], qfl[kt], bh1);
            }
        }

        // ---- scale + causal mask + online softmax ----
        #pragma unroll
        for (int nt = 0; nt < 8; ++nt) {
            sacc[nt][0] *= 0.125f; sacc[nt][1] *= 0.125f;
            sacc[nt][2] *= 0.125f; sacc[nt][3] *= 0.125f;
        }
        if (j0 == qt) {
            #pragma unroll
            for (int nt = 0; nt < 8; ++nt) {
                const int jc = nt * 8 + cloc;
                if (jc > rloc)     sacc[nt][0] = -INFINITY;
                if (jc + 1 > rloc) sacc[nt][1] = -INFINITY;
                if (jc > rloc + 8)     sacc[nt][2] = -INFINITY;
                if (jc + 1 > rloc + 8) sacc[nt][3] = -INFINITY;
            }
        }
        float mx0 = -INFINITY, mx1 = -INFINITY;
        #pragma unroll
        for (int nt = 0; nt < 8; ++nt) {
            mx0 = fmaxf(mx0, fmaxf(sacc[nt][0], sacc[nt][1]));
            mx1 = fmaxf(mx1, fmaxf(sacc[nt][2], sacc[nt][3]));
        }
        mx0 = fmaxf(mx0, __shfl_xor_sync(0xffffffffu, mx0, 1));
        mx0 = fmaxf(mx0, __shfl_xor_sync(0xffffffffu, mx0, 2));
        mx1 = fmaxf(mx1, __shfl_xor_sync(0xffffffffu, mx1, 1));
        mx1 = fmaxf(mx1, __shfl_xor_sync(0xffffffffu, mx1, 2));
        const float mn0 = fmaxf(m_r[0], mx0), mn1 = fmaxf(m_r[1], mx1);
        const float al0 = __expf(m_r[0] - mn0), al1 = __expf(m_r[1] - mn1);
        m_r[0] = mn0; m_r[1] = mn1;

        float rs0 = 0.f, rs1 = 0.f;
        #pragma unroll
        for (int nt = 0; nt < 8; ++nt) {
            sacc[nt][0] = __expf(sacc[nt][0] - mn0); rs0 += sacc[nt][0];
            sacc[nt][1] = __expf(sacc[nt][1] - mn0); rs0 += sacc[nt][1];
            sacc[nt][2] = __expf(sacc[nt][2] - mn1); rs1 += sacc[nt][2];
            sacc[nt][3] = __expf(sacc[nt][3] - mn1); rs1 += sacc[nt][3];
        }
        rs0 += __shfl_xor_sync(0xffffffffu, rs0, 1);
        rs0 += __shfl_xor_sync(0xffffffffu, rs0, 2);
        rs1 += __shfl_xor_sync(0xffffffffu, rs1, 1);
        rs1 += __shfl_xor_sync(0xffffffffu, rs1, 2);
        l_r[0] = l_r[0] * al0 + rs0;
        l_r[1] = l_r[1] * al1 + rs1;
        #pragma unroll
        for (int nt = 0; nt < 8; ++nt) {
            oacc[nt][0] *= al0; oacc[nt][1] *= al0;
            oacc[nt][2] *= al1; oacc[nt][3] *= al1;
        }

        // ---- O += P V (split 3-term; P frags straight from accum layout) ----
        #pragma unroll
        for (int kt = 0; kt < 4; ++kt) {
            uint32_t ph[4], pl[4];
            ph[0] = pack_hi(sacc[2 * kt][0], sacc[2 * kt][1]);
            ph[1] = pack_hi(sacc[2 * kt][2], sacc[2 * kt][3]);
            ph[2] = pack_hi(sacc[2 * kt + 1][0], sacc[2 * kt + 1][1]);
            ph[3] = pack_hi(sacc[2 * kt + 1][2], sacc[2 * kt + 1][3]);
            pl[0] = pack_lo(sacc[2 * kt][0], sacc[2 * kt][1]);
            pl[1] = pack_lo(sacc[2 * kt][2], sacc[2 * kt][3]);
            pl[2] = pack_lo(sacc[2 * kt + 1][0], sacc[2 * kt + 1][1]);
            pl[3] = pack_lo(sacc[2 * kt + 1][2], sacc[2 * kt + 1][3]);
            #pragma unroll
            for (int nj = 0; nj < 4; ++nj) {
                uint32_t v0, v1, v2, v3, w0, w1, w2, w3;
                const int off = kt * 16 * FST * 2 + nj * 32;
                ldsm4t(bVh + voffV + off, v0, v1, v2, v3);
                ldsm4t(bVl + voffV + off, w0, w1, w2, w3);
                uint32_t vh0[2] = { v0, v1 }, vh1[2] = { v2, v3 };
                uint32_t vl0[2] = { w0, w1 }, vl1[2] = { w2, w3 };
                mma16816(oacc[nj * 2], ph, vh0);
                mma16816(oacc[nj * 2], ph, vl0);
                mma16816(oacc[nj * 2], pl, vh0);
                mma16816(oacc[nj * 2 + 1], ph, vh1);
                mma16816(oacc[nj * 2 + 1], ph, vl1);
                mma16816(oacc[nj * 2 + 1], pl, vh1);
            }
        }
    }

    // ---- epilogue: O/l -> ahi/alo at [b, q, h*64 + d] ----
    const float inv0 = 1.f / l_r[0], inv1 = 1.f / l_r[1];
    const int qrow = q0 + rloc;
    #pragma unroll
    for (int nt = 0; nt < 8; ++nt) {
        const int col = h * HD + nt * 8 + cloc;
        const float v0 = oacc[nt][0] * inv0, v1 = oacc[nt][1] * inv0;
        const float v2 = oacc[nt][2] * inv1, v3 = oacc[nt][3] * inv1;
        const size_t r0 = ((size_t)b * SEQ + qrow) * EMB + col;
        const size_t r1 = ((size_t)b * SEQ + qrow + 8) * EMB + col;
        *(uint32_t*)&ahi[r0] = pack_hi(v0, v1);
        *(uint32_t*)&alo[r0] = pack_lo(v0, v1);
        *(uint32_t*)&ahi[r1] = pack_hi(v2, v3);
        *(uint32_t*)&alo[r1] = pack_lo(v2, v3);
    }
}

// ---------------------------------------------------------------------------
extern "C" void kernel_launch(void* const* d_in, const int* in_sizes, int n_in,
                              void* d_out, int out_size)
{
    const float* x    = (const float*)d_in[0];
    const float* Wqkv = (const float*)d_in[1];
    const float* bqkv = (const float*)d_in[2];
    const float* Wout = (const float*)d_in[3];
    const float* bout = (const float*)d_in[4];
    float* out = (float*)d_out;

    __nv_bfloat16 *xhi, *xlo, *w1hi, *w1lo, *w2hi, *w2lo, *qkvh, *qkvl, *ahi, *alo;
    cudaGetSymbolAddress((void**)&xhi, g_xhi);
    cudaGetSymbolAddress((void**)&xlo, g_xlo);
    cudaGetSymbolAddress((void**)&w1hi, g_w1hi);
    cudaGetSymbolAddress((void**)&w1lo, g_w1lo);
    cudaGetSymbolAddress((void**)&w2hi, g_w2hi);
    cudaGetSymbolAddress((void**)&w2lo, g_w2lo);
    cudaGetSymbolAddress((void**)&qkvh, g_qkvh);
    cudaGetSymbolAddress((void**)&qkvl, g_qkvl);
    cudaGetSymbolAddress((void**)&ahi, g_ahi);
    cudaGetSymbolAddress((void**)&alo, g_alo);

    cudaFuncSetAttribute(flash_mma,
                         cudaFuncAttributeMaxDynamicSharedMemorySize, FLASH_SMEM);

    const int nx  = BSZ * SEQ * EMB;
    const int nw1 = 3 * EMB * EMB;
    const int nw2 = EMB * EMB;

    // 0) input splits
    split_kernel<<<nx / 4 / 256, 256>>>((const float4*)x, (uint2*)xhi, (uint2*)xlo, nx / 4);
    split_kernel<<<nw1 / 4 / 256, 256>>>((const float4*)Wqkv, (uint2*)w1hi, (uint2*)w1lo, nw1 / 4);
    split_kernel<<<nw2 / 4 / 256, 256>>>((const float4*)Wout, (uint2*)w2hi, (uint2*)w2lo, nw2 / 4);

    // 1) qkv = x @ Wqkv^T + bqkv  -> bf16 hi/lo
    mma_gemm_bias<true><<<dim3(3 * EMB / 128, BSZ * SEQ / 128), 256>>>(
        xhi, xlo, w1hi, w1lo, bqkv, nullptr, qkvh, qkvl, BSZ * SEQ, 3 * EMB, EMB);

    // 2) tensor-core causal flash attention -> attn bf16 hi/lo
    flash_mma<<<dim3(SEQ / 64, NH, BSZ), 128, FLASH_SMEM>>>(qkvh, qkvl, ahi, alo);

    // 3) out = attn @ Wout^T + bout  (fp32 out)
    mma_gemm_bias<false><<<dim3(EMB / 128, BSZ * SEQ / 128), 256>>>(
        ahi, alo, w2hi, w2lo, bout, out, nullptr, nullptr, BSZ * SEQ, EMB, EMB);
}

// round 5
// speedup vs baseline: 2.7557x; 1.0464x over previous
#include <cuda_runtime.h>
#include <cuda_bf16.h>
#include <math.h>
#include <stdint.h>

#define BSZ 2
#define SEQ 2048
#define EMB 1024
#define NH  16
#define HD  64

// ---------------------------------------------------------------------------
// Scratch (__device__ globals)
// ---------------------------------------------------------------------------
__device__ __nv_bfloat16 g_xhi[(size_t)BSZ * SEQ * EMB];
__device__ __nv_bfloat16 g_xlo[(size_t)BSZ * SEQ * EMB];
__device__ __nv_bfloat16 g_w1hi[(size_t)3 * EMB * EMB];
__device__ __nv_bfloat16 g_w1lo[(size_t)3 * EMB * EMB];
__device__ __nv_bfloat16 g_w2hi[(size_t)EMB * EMB];
__device__ __nv_bfloat16 g_w2lo[(size_t)EMB * EMB];
__device__ __nv_bfloat16 g_qkvh[(size_t)BSZ * SEQ * 3 * EMB];
__device__ __nv_bfloat16 g_qkvl[(size_t)BSZ * SEQ * 3 * EMB];
__device__ __nv_bfloat16 g_ahi[(size_t)BSZ * SEQ * EMB];
__device__ __nv_bfloat16 g_alo[(size_t)BSZ * SEQ * EMB];

// ---------------------------------------------------------------------------
// fp32 -> (bf16 hi, bf16 lo)
// ---------------------------------------------------------------------------
__global__ __launch_bounds__(256) void split_kernel(
    const float4* __restrict__ in, uint2* __restrict__ hi,
    uint2* __restrict__ lo, int n4)
{
    int i = blockIdx.x * blockDim.x + threadIdx.x;
    if (i >= n4) return;
    float4 v = in[i];
    __nv_bfloat16 h0 = __float2bfloat16(v.x), h1 = __float2bfloat16(v.y);
    __nv_bfloat16 h2 = __float2bfloat16(v.z), h3 = __float2bfloat16(v.w);
    __nv_bfloat16 l0 = __float2bfloat16(v.x - __bfloat162float(h0));
    __nv_bfloat16 l1 = __float2bfloat16(v.y - __bfloat162float(h1));
    __nv_bfloat16 l2 = __float2bfloat16(v.z - __bfloat162float(h2));
    __nv_bfloat16 l3 = __float2bfloat16(v.w - __bfloat162float(h3));
    __nv_bfloat162 hA(h0, h1), hB(h2, h3), lA(l0, l1), lB(l2, l3);
    uint2 H, L;
    H.x = *reinterpret_cast<uint32_t*>(&hA); H.y = *reinterpret_cast<uint32_t*>(&hB);
    L.x = *reinterpret_cast<uint32_t*>(&lA); L.y = *reinterpret_cast<uint32_t*>(&lB);
    hi[i] = H; lo[i] = L;
}

// ---------------------------------------------------------------------------
// MMA / cp.async helpers
// ---------------------------------------------------------------------------
__device__ __forceinline__ void ldsm4(uint32_t a, uint32_t& r0, uint32_t& r1,
                                      uint32_t& r2, uint32_t& r3)
{
    asm volatile("ldmatrix.sync.aligned.m8n8.x4.shared.b16 {%0,%1,%2,%3}, [%4];\n"
                 : "=r"(r0), "=r"(r1), "=r"(r2), "=r"(r3) : "r"(a));
}
__device__ __forceinline__ void ldsm4t(uint32_t a, uint32_t& r0, uint32_t& r1,
                                       uint32_t& r2, uint32_t& r3)
{
    asm volatile("ldmatrix.sync.aligned.m8n8.x4.trans.shared.b16 {%0,%1,%2,%3}, [%4];\n"
                 : "=r"(r0), "=r"(r1), "=r"(r2), "=r"(r3) : "r"(a));
}
__device__ __forceinline__ void mma16816(float* d, const uint32_t* a, const uint32_t* b)
{
    asm volatile("mma.sync.aligned.m16n8k16.row.col.f32.bf16.bf16.f32 "
                 "{%0,%1,%2,%3}, {%4,%5,%6,%7}, {%8,%9}, {%0,%1,%2,%3};\n"
                 : "+f"(d[0]), "+f"(d[1]), "+f"(d[2]), "+f"(d[3])
                 : "r"(a[0]), "r"(a[1]), "r"(a[2]), "r"(a[3]), "r"(b[0]), "r"(b[1]));
}
__device__ __forceinline__ uint32_t pack_hi(float a, float b)
{
    __nv_bfloat162 p(__float2bfloat16(a), __float2bfloat16(b));
    return *reinterpret_cast<uint32_t*>(&p);
}
__device__ __forceinline__ uint32_t pack_lo(float a, float b)
{
    __nv_bfloat16 ha = __float2bfloat16(a), hb = __float2bfloat16(b);
    __nv_bfloat162 p(__float2bfloat16(a - __bfloat162float(ha)),
                     __float2bfloat16(b - __bfloat162float(hb)));
    return *reinterpret_cast<uint32_t*>(&p);
}
__device__ __forceinline__ void cp16(uint32_t saddr, const void* gaddr)
{
    asm volatile("cp.async.cg.shared.global [%0], [%1], 16;" :: "r"(saddr), "l"(gaddr));
}
#define CP_COMMIT() asm volatile("cp.async.commit_group;" ::: "memory")
#define CP_WAIT1()  asm volatile("cp.async.wait_group 1;" ::: "memory")
#define CP_WAIT0()  asm volatile("cp.async.wait_group 0;" ::: "memory")

// ---------------------------------------------------------------------------
// Split-bf16 GEMM: C = A·B^T + bias, 3-term compensation (Ah·Bh+Ah·Bl+Al·Bh).
// CTA 128x128, warp 64x32, K-chunks of 32 via a 2-stage cp.async pipeline.
// Smem row stride 40 bf16 (proven conflict-free for this ldmatrix pattern).
// __launch_bounds__(256,2): cp.async removes the gmem prefetch registers so
// 2 CTAs/SM (16 warps) fit -> latency hiding for the LDSM->HMMA chains.
// ---------------------------------------------------------------------------
#define SAST 40
#define GARR_B  (128 * SAST * 2)        // bytes per array (10240)
#define GSTG_B  (4 * GARR_B)            // bytes per stage (40960)
#define GEMM_SMEM (2 * GSTG_B)          // 81920

template<bool SPLIT_OUT>
__global__ __launch_bounds__(256, 2) void mma_gemm_bias(
    const __nv_bfloat16* __restrict__ Ahi, const __nv_bfloat16* __restrict__ Alo,
    const __nv_bfloat16* __restrict__ Bhi, const __nv_bfloat16* __restrict__ Blo,
    const float* __restrict__ bias, float* __restrict__ Cf,
    __nv_bfloat16* __restrict__ Chi, __nv_bfloat16* __restrict__ Clo,
    int M, int N, int K)
{
    extern __shared__ __align__(16) unsigned char gsm[];
    const uint32_t sb = (uint32_t)__cvta_generic_to_shared(gsm);

    const int tid = threadIdx.x, lane = tid & 31, wid = tid >> 5;
    const int wm = (wid >> 2) * 64;
    const int wn = (wid & 3) * 32;
    const int m0 = blockIdx.y * 128, n0 = blockIdx.x * 128;

    const int lrow = tid >> 1;              // 0..127
    const int lcol = (tid & 1) * 16;        // 0 or 16 (bf16 elements)
    const uint32_t so = (uint32_t)(lrow * SAST + lcol) * 2;
    const __nv_bfloat16* gAh = Ahi + (size_t)(m0 + lrow) * K + lcol;
    const __nv_bfloat16* gAl = Alo + (size_t)(m0 + lrow) * K + lcol;
    const __nv_bfloat16* gBh = Bhi + (size_t)(n0 + lrow) * K + lcol;
    const __nv_bfloat16* gBl = Blo + (size_t)(n0 + lrow) * K + lcol;

    const int aoff = ((wm + (lane & 15)) * SAST + (lane >> 4) * 8) * 2;
    const int boff = ((wn + (lane & 7) + ((lane >> 4) & 1) * 8) * SAST
                      + ((lane >> 3) & 1) * 8) * 2;

    float acc[4][4][4];
    #pragma unroll
    for (int i = 0; i < 4; ++i)
        #pragma unroll
        for (int j = 0; j < 4; ++j)
            acc[i][j][0] = acc[i][j][1] = acc[i][j][2] = acc[i][j][3] = 0.f;

    const int NCH = K / 32;

    // stage loader: chunk c into stage st
    auto load_stage = [&](int c, int st) {
        const int kc = c * 32;
        const uint32_t base = sb + st * GSTG_B + so;
        cp16(base,                    gAh + kc);
        cp16(base + 16,               gAh + kc + 8);
        cp16(base + GARR_B,           gAl + kc);
        cp16(base + GARR_B + 16,      gAl + kc + 8);
        cp16(base + 2 * GARR_B,       gBh + kc);
        cp16(base + 2 * GARR_B + 16,  gBh + kc + 8);
        cp16(base + 3 * GARR_B,       gBl + kc);
        cp16(base + 3 * GARR_B + 16,  gBl + kc + 8);
        CP_COMMIT();
    };

    load_stage(0, 0);
    load_stage(1, 1);

    for (int c = 0; c < NCH; ++c) {
        if (c == NCH - 1) { CP_WAIT0(); } else { CP_WAIT1(); }
        __syncthreads();

        const int st = c & 1;
        const uint32_t bAh = sb + st * GSTG_B;
        const uint32_t bAl = bAh + GARR_B;
        const uint32_t bBh = bAh + 2 * GARR_B;
        const uint32_t bBl = bAh + 3 * GARR_B;

        #pragma unroll
        for (int ks = 0; ks < 2; ++ks) {
            const int kb = ks * 32;   // 16 bf16 = 32 bytes
            uint32_t ah[4][4], al[4][4], bh[4][2], bl[4][2];
            #pragma unroll
            for (int mi = 0; mi < 4; ++mi) {
                const int mo = mi * 16 * SAST * 2 + kb;
                ldsm4(bAh + aoff + mo, ah[mi][0], ah[mi][1], ah[mi][2], ah[mi][3]);
                ldsm4(bAl + aoff + mo, al[mi][0], al[mi][1], al[mi][2], al[mi][3]);
            }
            #pragma unroll
            for (int nj = 0; nj < 2; ++nj) {
                const int no = nj * 16 * SAST * 2 + kb;
                uint32_t t0, t1, t2, t3;
                ldsm4(bBh + boff + no, t0, t1, t2, t3);
                bh[nj * 2][0] = t0; bh[nj * 2][1] = t1;
                bh[nj * 2 + 1][0] = t2; bh[nj * 2 + 1][1] = t3;
                ldsm4(bBl + boff + no, t0, t1, t2, t3);
                bl[nj * 2][0] = t0; bl[nj * 2][1] = t1;
                bl[nj * 2 + 1][0] = t2; bl[nj * 2 + 1][1] = t3;
            }
            #pragma unroll
            for (int mi = 0; mi < 4; ++mi)
                #pragma unroll
                for (int ni = 0; ni < 4; ++ni) {
                    mma16816(acc[mi][ni], ah[mi], bh[ni]);
                    mma16816(acc[mi][ni], ah[mi], bl[ni]);
                    mma16816(acc[mi][ni], al[mi], bh[ni]);
                }
        }
        __syncthreads();
        if (c + 2 < NCH) load_stage(c + 2, st);
    }

    const int rbase = m0 + wm + (lane >> 2);
    const int cbase = n0 + wn + (lane & 3) * 2;
    #pragma unroll
    for (int mi = 0; mi < 4; ++mi) {
        const int r = rbase + mi * 16;
        #pragma unroll
        for (int ni = 0; ni < 4; ++ni) {
            const int c = cbase + ni * 8;
            const float b0 = bias[c], b1 = bias[c + 1];
            const float v0 = acc[mi][ni][0] + b0, v1 = acc[mi][ni][1] + b1;
            const float v2 = acc[mi][ni][2] + b0, v3 = acc[mi][ni][3] + b1;
            if (SPLIT_OUT) {
                *(uint32_t*)&Chi[(size_t)r * N + c]       = pack_hi(v0, v1);
                *(uint32_t*)&Clo[(size_t)r * N + c]       = pack_lo(v0, v1);
                *(uint32_t*)&Chi[(size_t)(r + 8) * N + c] = pack_hi(v2, v3);
                *(uint32_t*)&Clo[(size_t)(r + 8) * N + c] = pack_lo(v2, v3);
            } else {
                float2 o0 = { v0, v1 }, o1 = { v2, v3 };
                *(float2*)&Cf[(size_t)r * N + c] = o0;
                *(float2*)&Cf[(size_t)(r + 8) * N + c] = o1;
            }
        }
    }
}

// ---------------------------------------------------------------------------
// Tensor-core flash attention (unchanged from R3 — proven).
// ---------------------------------------------------------------------------
#define FST 72
#define FLASH_SMEM (6 * 64 * FST * 2)

__global__ __launch_bounds__(128) void flash_mma(
    const __nv_bfloat16* __restrict__ qkvh,
    const __nv_bfloat16* __restrict__ qkvl,
    __nv_bfloat16* __restrict__ ahi, __nv_bfloat16* __restrict__ alo)
{
    extern __shared__ __nv_bfloat16 fsm[];
    __nv_bfloat16* sQh = fsm;
    __nv_bfloat16* sQl = fsm + 64 * FST;
    __nv_bfloat16* sKh = fsm + 2 * 64 * FST;
    __nv_bfloat16* sKl = fsm + 3 * 64 * FST;
    __nv_bfloat16* sVh = fsm + 4 * 64 * FST;
    __nv_bfloat16* sVl = fsm + 5 * 64 * FST;

    const int b = blockIdx.z, h = blockIdx.y, qt = blockIdx.x;
    const int tid = threadIdx.x, lane = tid & 31, wid = tid >> 5;
    const size_t bbase = (size_t)b * SEQ * 3 * EMB;
    const int hbase = h * SEQ * HD;
    const int q0 = qt * 64;

    #pragma unroll
    for (int i = 0; i < 4; ++i) {
        const int id = tid + 128 * i;
        const int r = id >> 3, c = (id & 7) * 8;
        const int f = hbase + (q0 + r) * HD + c;
        const size_t ga = bbase + (size_t)(f >> 10) * 3072 + (f & 1023);
        *(uint4*)&sQh[r * FST + c] = *(const uint4*)&qkvh[ga];
        *(uint4*)&sQl[r * FST + c] = *(const uint4*)&qkvl[ga];
    }
    __syncthreads();

    const uint32_t bQh = (uint32_t)__cvta_generic_to_shared(sQh);
    const uint32_t bQl = (uint32_t)__cvta_generic_to_shared(sQl);
    const uint32_t bKh = (uint32_t)__cvta_generic_to_shared(sKh);
    const uint32_t bKl = (uint32_t)__cvta_generic_to_shared(sKl);
    const uint32_t bVh = (uint32_t)__cvta_generic_to_shared(sVh);
    const uint32_t bVl = (uint32_t)__cvta_generic_to_shared(sVl);

    const int aoff = ((wid * 16 + (lane & 15)) * FST + (lane >> 4) * 8) * 2;
    uint32_t qfh[4][4], qfl[4][4];
    #pragma unroll
    for (int kt = 0; kt < 4; ++kt) {
        ldsm4(bQh + aoff + kt * 32, qfh[kt][0], qfh[kt][1], qfh[kt][2], qfh[kt][3]);
        ldsm4(bQl + aoff + kt * 32, qfl[kt][0], qfl[kt][1], qfl[kt][2], qfl[kt][3]);
    }

    const int boffK = (((lane & 7) + ((lane >> 4) & 1) * 8) * FST + ((lane >> 3) & 1) * 8) * 2;
    const int voffV = (((lane & 7) + ((lane >> 3) & 1) * 8) * FST + (lane >> 4) * 8) * 2;

    float m_r[2] = { -INFINITY, -INFINITY };
    float l_r[2] = { 0.f, 0.f };
    float oacc[8][4];
    #pragma unroll
    for (int nt = 0; nt < 8; ++nt)
        oacc[nt][0] = oacc[nt][1] = oacc[nt][2] = oacc[nt][3] = 0.f;

    const int rloc = wid * 16 + (lane >> 2);
    const int cloc = 2 * (lane & 3);

    for (int j0 = 0; j0 <= qt; ++j0) {
        __syncthreads();
        #pragma unroll
        for (int i = 0; i < 4; ++i) {
            const int id = tid + 128 * i;
            const int r = id >> 3, c = (id & 7) * 8;
            const int f = hbase + (j0 * 64 + r) * HD + c;
            const size_t ga = bbase + (size_t)(f >> 10) * 3072 + (f & 1023);
            *(uint4*)&sKh[r * FST + c] = *(const uint4*)&qkvh[ga + 1024];
            *(uint4*)&sKl[r * FST + c] = *(const uint4*)&qkvl[ga + 1024];
            *(uint4*)&sVh[r * FST + c] = *(const uint4*)&qkvh[ga + 2048];
            *(uint4*)&sVl[r * FST + c] = *(const uint4*)&qkvl[ga + 2048];
        }
        __syncthreads();

        float sacc[8][4];
        #pragma unroll
        for (int nt = 0; nt < 8; ++nt)
            sacc[nt][0] = sacc[nt][1] = sacc[nt][2] = sacc[nt][3] = 0.f;

        #pragma unroll
        for (int kt = 0; kt < 4; ++kt) {
            #pragma unroll
            for (int nj = 0; nj < 4; ++nj) {
                uint32_t h0, h1, h2, h3, l0, l1, l2, l3;
                const int off = nj * 16 * FST * 2 + kt * 32;
                ldsm4(bKh + boffK + off, h0, h1, h2, h3);
                ldsm4(bKl + boffK + off, l0, l1, l2, l3);
                uint32_t bh0[2] = { h0, h1 }, bh1[2] = { h2, h3 };
                uint32_t bl0[2] = { l0, l1 }, bl1[2] = { l2, l3 };
                mma16816(sacc[nj * 2], qfh[kt], bh0);
                mma16816(sacc[nj * 2], qfh[kt], bl0);
                mma16816(sacc[nj * 2], qfl[kt], bh0);
                mma16816(sacc[nj * 2 + 1], qfh[kt], bh1);
                mma16816(sacc[nj * 2 + 1], qfh[kt], bl1);
                mma16816(sacc[nj * 2 + 1], qfl[kt], bh1);
            }
        }

        #pragma unroll
        for (int nt = 0; nt < 8; ++nt) {
            sacc[nt][0] *= 0.125f; sacc[nt][1] *= 0.125f;
            sacc[nt][2] *= 0.125f; sacc[nt][3] *= 0.125f;
        }
        if (j0 == qt) {
            #pragma unroll
            for (int nt = 0; nt < 8; ++nt) {
                const int jc = nt * 8 + cloc;
                if (jc > rloc)     sacc[nt][0] = -INFINITY;
                if (jc + 1 > rloc) sacc[nt][1] = -INFINITY;
                if (jc > rloc + 8)     sacc[nt][2] = -INFINITY;
                if (jc + 1 > rloc + 8) sacc[nt][3] = -INFINITY;
            }
        }
        float mx0 = -INFINITY, mx1 = -INFINITY;
        #pragma unroll
        for (int nt = 0; nt < 8; ++nt) {
            mx0 = fmaxf(mx0, fmaxf(sacc[nt][0], sacc[nt][1]));
            mx1 = fmaxf(mx1, fmaxf(sacc[nt][2], sacc[nt][3]));
        }
        mx0 = fmaxf(mx0, __shfl_xor_sync(0xffffffffu, mx0, 1));
        mx0 = fmaxf(mx0, __shfl_xor_sync(0xffffffffu, mx0, 2));
        mx1 = fmaxf(mx1, __shfl_xor_sync(0xffffffffu, mx1, 1));
        mx1 = fmaxf(mx1, __shfl_xor_sync(0xffffffffu, mx1, 2));
        const float mn0 = fmaxf(m_r[0], mx0), mn1 = fmaxf(m_r[1], mx1);
        const float al0 = __expf(m_r[0] - mn0), al1 = __expf(m_r[1] - mn1);
        m_r[0] = mn0; m_r[1] = mn1;

        float rs0 = 0.f, rs1 = 0.f;
        #pragma unroll
        for (int nt = 0; nt < 8; ++nt) {
            sacc[nt][0] = __expf(sacc[nt][0] - mn0); rs0 += sacc[nt][0];
            sacc[nt][1] = __expf(sacc[nt][1] - mn0); rs0 += sacc[nt][1];
            sacc[nt][2] = __expf(sacc[nt][2] - mn1); rs1 += sacc[nt][2];
            sacc[nt][3] = __expf(sacc[nt][3] - mn1); rs1 += sacc[nt][3];
        }
        rs0 += __shfl_xor_sync(0xffffffffu, rs0, 1);
        rs0 += __shfl_xor_sync(0xffffffffu, rs0, 2);
        rs1 += __shfl_xor_sync(0xffffffffu, rs1, 1);
        rs1 += __shfl_xor_sync(0xffffffffu, rs1, 2);
        l_r[0] = l_r[0] * al0 + rs0;
        l_r[1] = l_r[1] * al1 + rs1;
        #pragma unroll
        for (int nt = 0; nt < 8; ++nt) {
            oacc[nt][0] *= al0; oacc[nt][1] *= al0;
            oacc[nt][2] *= al1; oacc[nt][3] *= al1;
        }

        #pragma unroll
        for (int kt = 0; kt < 4; ++kt) {
            uint32_t ph[4], pl[4];
            ph[0] = pack_hi(sacc[2 * kt][0], sacc[2 * kt][1]);
            ph[1] = pack_hi(sacc[2 * kt][2], sacc[2 * kt][3]);
            ph[2] = pack_hi(sacc[2 * kt + 1][0], sacc[2 * kt + 1][1]);
            ph[3] = pack_hi(sacc[2 * kt + 1][2], sacc[2 * kt + 1][3]);
            pl[0] = pack_lo(sacc[2 * kt][0], sacc[2 * kt][1]);
            pl[1] = pack_lo(sacc[2 * kt][2], sacc[2 * kt][3]);
            pl[2] = pack_lo(sacc[2 * kt + 1][0], sacc[2 * kt + 1][1]);
            pl[3] = pack_lo(sacc[2 * kt + 1][2], sacc[2 * kt + 1][3]);
            #pragma unroll
            for (int nj = 0; nj < 4; ++nj) {
                uint32_t v0, v1, v2, v3, w0, w1, w2, w3;
                const int off = kt * 16 * FST * 2 + nj * 32;
                ldsm4t(bVh + voffV + off, v0, v1, v2, v3);
                ldsm4t(bVl + voffV + off, w0, w1, w2, w3);
                uint32_t vh0[2] = { v0, v1 }, vh1[2] = { v2, v3 };
                uint32_t vl0[2] = { w0, w1 }, vl1[2] = { w2, w3 };
                mma16816(oacc[nj * 2], ph, vh0);
                mma16816(oacc[nj * 2], ph, vl0);
                mma16816(oacc[nj * 2], pl, vh0);
                mma16816(oacc[nj * 2 + 1], ph, vh1);
                mma16816(oacc[nj * 2 + 1], ph, vl1);
                mma16816(oacc[nj * 2 + 1], pl, vh1);
            }
        }
    }

    const float inv0 = 1.f / l_r[0], inv1 = 1.f / l_r[1];
    const int qrow = q0 + rloc;
    #pragma unroll
    for (int nt = 0; nt < 8; ++nt) {
        const int col = h * HD + nt * 8 + cloc;
        const float v0 = oacc[nt][0] * inv0, v1 = oacc[nt][1] * inv0;
        const float v2 = oacc[nt][2] * inv1, v3 = oacc[nt][3] * inv1;
        const size_t r0 = ((size_t)b * SEQ + qrow) * EMB + col;
        const size_t r1 = ((size_t)b * SEQ + qrow + 8) * EMB + col;
        *(uint32_t*)&ahi[r0] = pack_hi(v0, v1);
        *(uint32_t*)&alo[r0] = pack_lo(v0, v1);
        *(uint32_t*)&ahi[r1] = pack_hi(v2, v3);
        *(uint32_t*)&alo[r1] = pack_lo(v2, v3);
    }
}

// ---------------------------------------------------------------------------
extern "C" void kernel_launch(void* const* d_in, const int* in_sizes, int n_in,
                              void* d_out, int out_size)
{
    const float* x    = (const float*)d_in[0];
    const float* Wqkv = (const float*)d_in[1];
    const float* bqkv = (const float*)d_in[2];
    const float* Wout = (const float*)d_in[3];
    const float* bout = (const float*)d_in[4];
    float* out = (float*)d_out;

    __nv_bfloat16 *xhi, *xlo, *w1hi, *w1lo, *w2hi, *w2lo, *qkvh, *qkvl, *ahi, *alo;
    cudaGetSymbolAddress((void**)&xhi, g_xhi);
    cudaGetSymbolAddress((void**)&xlo, g_xlo);
    cudaGetSymbolAddress((void**)&w1hi, g_w1hi);
    cudaGetSymbolAddress((void**)&w1lo, g_w1lo);
    cudaGetSymbolAddress((void**)&w2hi, g_w2hi);
    cudaGetSymbolAddress((void**)&w2lo, g_w2lo);
    cudaGetSymbolAddress((void**)&qkvh, g_qkvh);
    cudaGetSymbolAddress((void**)&qkvl, g_qkvl);
    cudaGetSymbolAddress((void**)&ahi, g_ahi);
    cudaGetSymbolAddress((void**)&alo, g_alo);

    cudaFuncSetAttribute(flash_mma,
                         cudaFuncAttributeMaxDynamicSharedMemorySize, FLASH_SMEM);
    cudaFuncSetAttribute(mma_gemm_bias<true>,
                         cudaFuncAttributeMaxDynamicSharedMemorySize, GEMM_SMEM);
    cudaFuncSetAttribute(mma_gemm_bias<false>,
                         cudaFuncAttributeMaxDynamicSharedMemorySize, GEMM_SMEM);

    const int nx  = BSZ * SEQ * EMB;
    const int nw1 = 3 * EMB * EMB;
    const int nw2 = EMB * EMB;

    // 0) input splits
    split_kernel<<<nx / 4 / 256, 256>>>((const float4*)x, (uint2*)xhi, (uint2*)xlo, nx / 4);
    split_kernel<<<nw1 / 4 / 256, 256>>>((const float4*)Wqkv, (uint2*)w1hi, (uint2*)w1lo, nw1 / 4);
    split_kernel<<<nw2 / 4 / 256, 256>>>((const float4*)Wout, (uint2*)w2hi, (uint2*)w2lo, nw2 / 4);

    // 1) qkv = x @ Wqkv^T + bqkv  -> bf16 hi/lo
    mma_gemm_bias<true><<<dim3(3 * EMB / 128, BSZ * SEQ / 128), 256, GEMM_SMEM>>>(
        xhi, xlo, w1hi, w1lo, bqkv, nullptr, qkvh, qkvl, BSZ * SEQ, 3 * EMB, EMB);

    // 2) tensor-core causal flash attention -> attn bf16 hi/lo
    flash_mma<<<dim3(SEQ / 64, NH, BSZ), 128, FLASH_SMEM>>>(qkvh, qkvl, ahi, alo);

    // 3) out = attn @ Wout^T + bout  (fp32 out)
    mma_gemm_bias<false><<<dim3(EMB / 128, BSZ * SEQ / 128), 256, GEMM_SMEM>>>(
        ahi, alo, w2hi, w2lo, bout, out, nullptr, nullptr, BSZ * SEQ, EMB, EMB);
}

// round 6
// speedup vs baseline: 3.6264x; 1.3159x over previous
#include <cuda_runtime.h>
#include <cuda_fp16.h>
#include <math.h>
#include <stdint.h>

#define BSZ 2
#define SEQ 2048
#define EMB 1024
#define NH  16
#define HD  64

// ---------------------------------------------------------------------------
// Scratch (__device__ globals)
// ---------------------------------------------------------------------------
__device__ __half g_xh[(size_t)BSZ * SEQ * EMB];            // x fp16
__device__ __half g_w1h[(size_t)3 * EMB * EMB];
__device__ __half g_w1l[(size_t)3 * EMB * EMB];
__device__ __half g_w2h[(size_t)EMB * EMB];
__device__ __half g_w2l[(size_t)EMB * EMB];
__device__ __half g_qkvh[(size_t)BSZ * SEQ * 3 * EMB];
__device__ __half g_qkvl[(size_t)BSZ * SEQ * 3 * EMB];
__device__ __half g_ah[(size_t)BSZ * SEQ * EMB];            // attn fp16 (hi only)

// ---------------------------------------------------------------------------
// fp32 -> fp16 convert / split
// ---------------------------------------------------------------------------
__global__ __launch_bounds__(256) void conv_kernel(
    const float4* __restrict__ in, uint2* __restrict__ hi, int n4)
{
    int i = blockIdx.x * blockDim.x + threadIdx.x;
    if (i >= n4) return;
    float4 v = in[i];
    __half2 a(__float2half_rn(v.x), __float2half_rn(v.y));
    __half2 b(__float2half_rn(v.z), __float2half_rn(v.w));
    uint2 H;
    H.x = *reinterpret_cast<uint32_t*>(&a);
    H.y = *reinterpret_cast<uint32_t*>(&b);
    hi[i] = H;
}

__global__ __launch_bounds__(256) void split_kernel(
    const float4* __restrict__ in, uint2* __restrict__ hi,
    uint2* __restrict__ lo, int n4)
{
    int i = blockIdx.x * blockDim.x + threadIdx.x;
    if (i >= n4) return;
    float4 v = in[i];
    __half h0 = __float2half_rn(v.x), h1 = __float2half_rn(v.y);
    __half h2 = __float2half_rn(v.z), h3 = __float2half_rn(v.w);
    __half l0 = __float2half_rn(v.x - __half2float(h0));
    __half l1 = __float2half_rn(v.y - __half2float(h1));
    __half l2 = __float2half_rn(v.z - __half2float(h2));
    __half l3 = __float2half_rn(v.w - __half2float(h3));
    __half2 hA(h0, h1), hB(h2, h3), lA(l0, l1), lB(l2, l3);
    uint2 H, L;
    H.x = *reinterpret_cast<uint32_t*>(&hA); H.y = *reinterpret_cast<uint32_t*>(&hB);
    L.x = *reinterpret_cast<uint32_t*>(&lA); L.y = *reinterpret_cast<uint32_t*>(&lB);
    hi[i] = H; lo[i] = L;
}

// ---------------------------------------------------------------------------
// MMA / cp.async helpers (fp16)
// ---------------------------------------------------------------------------
__device__ __forceinline__ void ldsm4(uint32_t a, uint32_t& r0, uint32_t& r1,
                                      uint32_t& r2, uint32_t& r3)
{
    asm volatile("ldmatrix.sync.aligned.m8n8.x4.shared.b16 {%0,%1,%2,%3}, [%4];\n"
                 : "=r"(r0), "=r"(r1), "=r"(r2), "=r"(r3) : "r"(a));
}
__device__ __forceinline__ void ldsm4t(uint32_t a, uint32_t& r0, uint32_t& r1,
                                       uint32_t& r2, uint32_t& r3)
{
    asm volatile("ldmatrix.sync.aligned.m8n8.x4.trans.shared.b16 {%0,%1,%2,%3}, [%4];\n"
                 : "=r"(r0), "=r"(r1), "=r"(r2), "=r"(r3) : "r"(a));
}
__device__ __forceinline__ void mma16816(float* d, const uint32_t* a, const uint32_t* b)
{
    asm volatile("mma.sync.aligned.m16n8k16.row.col.f32.f16.f16.f32 "
                 "{%0,%1,%2,%3}, {%4,%5,%6,%7}, {%8,%9}, {%0,%1,%2,%3};\n"
                 : "+f"(d[0]), "+f"(d[1]), "+f"(d[2]), "+f"(d[3])
                 : "r"(a[0]), "r"(a[1]), "r"(a[2]), "r"(a[3]), "r"(b[0]), "r"(b[1]));
}
__device__ __forceinline__ uint32_t pack_h(float a, float b)
{
    __half2 p(__float2half_rn(a), __float2half_rn(b));
    return *reinterpret_cast<uint32_t*>(&p);
}
__device__ __forceinline__ uint32_t pack_l(float a, float b)
{
    __half ha = __float2half_rn(a), hb = __float2half_rn(b);
    __half2 p(__float2half_rn(a - __half2float(ha)),
              __float2half_rn(b - __half2float(hb)));
    return *reinterpret_cast<uint32_t*>(&p);
}
__device__ __forceinline__ void cp16(uint32_t saddr, const void* gaddr)
{
    asm volatile("cp.async.cg.shared.global [%0], [%1], 16;" :: "r"(saddr), "l"(gaddr));
}
#define CP_COMMIT() asm volatile("cp.async.commit_group;" ::: "memory")
#define CP_WAIT1()  asm volatile("cp.async.wait_group 1;" ::: "memory")
#define CP_WAIT0()  asm volatile("cp.async.wait_group 0;" ::: "memory")

// ---------------------------------------------------------------------------
// fp16 2-term GEMM:  C = A·B^T + bias ≈ Ah·Bh^T + Ah·Bl^T
// (A in fp16, B pre-split hi/lo; residual = Al·B ~ 2^-11 relative.)
// CTA 128x128, warp 64x32, 2-stage cp.async pipeline, 2 CTAs/SM.
// ---------------------------------------------------------------------------
#define SAST 40
#define GARR_B  (128 * SAST * 2)        // 10240 B per array
#define GSTG_B  (3 * GARR_B)            // 30720 B per stage (Ah, Bh, Bl)
#define GEMM_SMEM (2 * GSTG_B)          // 61440

template<bool SPLIT_OUT>
__global__ __launch_bounds__(256, 2) void mma_gemm_bias(
    const __half* __restrict__ Ah,
    const __half* __restrict__ Bhi, const __half* __restrict__ Blo,
    const float* __restrict__ bias, float* __restrict__ Cf,
    __half* __restrict__ Chi, __half* __restrict__ Clo,
    int M, int N, int K)
{
    extern __shared__ __align__(16) unsigned char gsm[];
    const uint32_t sb = (uint32_t)__cvta_generic_to_shared(gsm);

    const int tid = threadIdx.x, lane = tid & 31, wid = tid >> 5;
    const int wm = (wid >> 2) * 64;
    const int wn = (wid & 3) * 32;
    const int m0 = blockIdx.y * 128, n0 = blockIdx.x * 128;

    const int lrow = tid >> 1;
    const int lcol = (tid & 1) * 16;
    const uint32_t so = (uint32_t)(lrow * SAST + lcol) * 2;
    const __half* gAh = Ah  + (size_t)(m0 + lrow) * K + lcol;
    const __half* gBh = Bhi + (size_t)(n0 + lrow) * K + lcol;
    const __half* gBl = Blo + (size_t)(n0 + lrow) * K + lcol;

    const int aoff = ((wm + (lane & 15)) * SAST + (lane >> 4) * 8) * 2;
    const int boff = ((wn + (lane & 7) + ((lane >> 4) & 1) * 8) * SAST
                      + ((lane >> 3) & 1) * 8) * 2;

    float acc[4][4][4];
    #pragma unroll
    for (int i = 0; i < 4; ++i)
        #pragma unroll
        for (int j = 0; j < 4; ++j)
            acc[i][j][0] = acc[i][j][1] = acc[i][j][2] = acc[i][j][3] = 0.f;

    const int NCH = K / 32;

    auto load_stage = [&](int c, int st) {
        const int kc = c * 32;
        const uint32_t base = sb + st * GSTG_B + so;
        cp16(base,                    gAh + kc);
        cp16(base + 16,               gAh + kc + 8);
        cp16(base + GARR_B,           gBh + kc);
        cp16(base + GARR_B + 16,      gBh + kc + 8);
        cp16(base + 2 * GARR_B,       gBl + kc);
        cp16(base + 2 * GARR_B + 16,  gBl + kc + 8);
        CP_COMMIT();
    };

    load_stage(0, 0);
    load_stage(1, 1);

    for (int c = 0; c < NCH; ++c) {
        if (c == NCH - 1) { CP_WAIT0(); } else { CP_WAIT1(); }
        __syncthreads();

        const int st = c & 1;
        const uint32_t bAh = sb + st * GSTG_B;
        const uint32_t bBh = bAh + GARR_B;
        const uint32_t bBl = bAh + 2 * GARR_B;

        #pragma unroll
        for (int ks = 0; ks < 2; ++ks) {
            const int kb = ks * 32;
            uint32_t a[4][4], bh[4][2], bl[4][2];
            #pragma unroll
            for (int mi = 0; mi < 4; ++mi) {
                const int mo = mi * 16 * SAST * 2 + kb;
                ldsm4(bAh + aoff + mo, a[mi][0], a[mi][1], a[mi][2], a[mi][3]);
            }
            #pragma unroll
            for (int nj = 0; nj < 2; ++nj) {
                const int no = nj * 16 * SAST * 2 + kb;
                uint32_t t0, t1, t2, t3;
                ldsm4(bBh + boff + no, t0, t1, t2, t3);
                bh[nj * 2][0] = t0; bh[nj * 2][1] = t1;
                bh[nj * 2 + 1][0] = t2; bh[nj * 2 + 1][1] = t3;
                ldsm4(bBl + boff + no, t0, t1, t2, t3);
                bl[nj * 2][0] = t0; bl[nj * 2][1] = t1;
                bl[nj * 2 + 1][0] = t2; bl[nj * 2 + 1][1] = t3;
            }
            #pragma unroll
            for (int mi = 0; mi < 4; ++mi)
                #pragma unroll
                for (int ni = 0; ni < 4; ++ni) {
                    mma16816(acc[mi][ni], a[mi], bh[ni]);
                    mma16816(acc[mi][ni], a[mi], bl[ni]);
                }
        }
        __syncthreads();
        if (c + 2 < NCH) load_stage(c + 2, st);
    }

    const int rbase = m0 + wm + (lane >> 2);
    const int cbase = n0 + wn + (lane & 3) * 2;
    #pragma unroll
    for (int mi = 0; mi < 4; ++mi) {
        const int r = rbase + mi * 16;
        #pragma unroll
        for (int ni = 0; ni < 4; ++ni) {
            const int c = cbase + ni * 8;
            const float b0 = bias[c], b1 = bias[c + 1];
            const float v0 = acc[mi][ni][0] + b0, v1 = acc[mi][ni][1] + b1;
            const float v2 = acc[mi][ni][2] + b0, v3 = acc[mi][ni][3] + b1;
            if (SPLIT_OUT) {
                *(uint32_t*)&Chi[(size_t)r * N + c]       = pack_h(v0, v1);
                *(uint32_t*)&Clo[(size_t)r * N + c]       = pack_l(v0, v1);
                *(uint32_t*)&Chi[(size_t)(r + 8) * N + c] = pack_h(v2, v3);
                *(uint32_t*)&Clo[(size_t)(r + 8) * N + c] = pack_l(v2, v3);
            } else {
                float2 o0 = { v0, v1 }, o1 = { v2, v3 };
                *(float2*)&Cf[(size_t)r * N + c] = o0;
                *(float2*)&Cf[(size_t)(r + 8) * N + c] = o1;
            }
        }
    }
}

// ---------------------------------------------------------------------------
// fp16 2-term flash attention (causal, no-transpose head reshape).
// S = Qh·(Kh+Kl);  O = Ph·(Vh+Vl).   Residuals (Ql·K, Pl·V) ~ 2^-11.
// ---------------------------------------------------------------------------
#define FST 72
#define FLASH_SMEM (5 * 64 * FST * 2)

__global__ __launch_bounds__(128) void flash_mma(
    const __half* __restrict__ qkvh, const __half* __restrict__ qkvl,
    __half* __restrict__ attn)
{
    extern __shared__ __half fsm[];
    __half* sQ  = fsm;
    __half* sKh = fsm + 1 * 64 * FST;
    __half* sKl = fsm + 2 * 64 * FST;
    __half* sVh = fsm + 3 * 64 * FST;
    __half* sVl = fsm + 4 * 64 * FST;

    const int b = blockIdx.z, h = blockIdx.y, qt = blockIdx.x;
    const int tid = threadIdx.x, lane = tid & 31, wid = tid >> 5;
    const size_t bbase = (size_t)b * SEQ * 3 * EMB;
    const int hbase = h * SEQ * HD;
    const int q0 = qt * 64;

    #pragma unroll
    for (int i = 0; i < 4; ++i) {
        const int id = tid + 128 * i;
        const int r = id >> 3, c = (id & 7) * 8;
        const int f = hbase + (q0 + r) * HD + c;
        const size_t ga = bbase + (size_t)(f >> 10) * 3072 + (f & 1023);
        *(uint4*)&sQ[r * FST + c] = *(const uint4*)&qkvh[ga];
    }
    __syncthreads();

    const uint32_t bQ  = (uint32_t)__cvta_generic_to_shared(sQ);
    const uint32_t bKh = (uint32_t)__cvta_generic_to_shared(sKh);
    const uint32_t bKl = (uint32_t)__cvta_generic_to_shared(sKl);
    const uint32_t bVh = (uint32_t)__cvta_generic_to_shared(sVh);
    const uint32_t bVl = (uint32_t)__cvta_generic_to_shared(sVl);

    const int aoff = ((wid * 16 + (lane & 15)) * FST + (lane >> 4) * 8) * 2;
    uint32_t qf[4][4];
    #pragma unroll
    for (int kt = 0; kt < 4; ++kt)
        ldsm4(bQ + aoff + kt * 32, qf[kt][0], qf[kt][1], qf[kt][2], qf[kt][3]);

    const int boffK = (((lane & 7) + ((lane >> 4) & 1) * 8) * FST + ((lane >> 3) & 1) * 8) * 2;
    const int voffV = (((lane & 7) + ((lane >> 3) & 1) * 8) * FST + (lane >> 4) * 8) * 2;

    float m_r[2] = { -INFINITY, -INFINITY };
    float l_r[2] = { 0.f, 0.f };
    float oacc[8][4];
    #pragma unroll
    for (int nt = 0; nt < 8; ++nt)
        oacc[nt][0] = oacc[nt][1] = oacc[nt][2] = oacc[nt][3] = 0.f;

    const int rloc = wid * 16 + (lane >> 2);
    const int cloc = 2 * (lane & 3);

    for (int j0 = 0; j0 <= qt; ++j0) {
        __syncthreads();
        #pragma unroll
        for (int i = 0; i < 4; ++i) {
            const int id = tid + 128 * i;
            const int r = id >> 3, c = (id & 7) * 8;
            const int f = hbase + (j0 * 64 + r) * HD + c;
            const size_t ga = bbase + (size_t)(f >> 10) * 3072 + (f & 1023);
            *(uint4*)&sKh[r * FST + c] = *(const uint4*)&qkvh[ga + 1024];
            *(uint4*)&sKl[r * FST + c] = *(const uint4*)&qkvl[ga + 1024];
            *(uint4*)&sVh[r * FST + c] = *(const uint4*)&qkvh[ga + 2048];
            *(uint4*)&sVl[r * FST + c] = *(const uint4*)&qkvl[ga + 2048];
        }
        __syncthreads();

        float sacc[8][4];
        #pragma unroll
        for (int nt = 0; nt < 8; ++nt)
            sacc[nt][0] = sacc[nt][1] = sacc[nt][2] = sacc[nt][3] = 0.f;

        #pragma unroll
        for (int kt = 0; kt < 4; ++kt) {
            #pragma unroll
            for (int nj = 0; nj < 4; ++nj) {
                uint32_t h0, h1, h2, h3, l0, l1, l2, l3;
                const int off = nj * 16 * FST * 2 + kt * 32;
                ldsm4(bKh + boffK + off, h0, h1, h2, h3);
                ldsm4(bKl + boffK + off, l0, l1, l2, l3);
                uint32_t bh0[2] = { h0, h1 }, bh1[2] = { h2, h3 };
                uint32_t bl0[2] = { l0, l1 }, bl1[2] = { l2, l3 };
                mma16816(sacc[nj * 2], qf[kt], bh0);
                mma16816(sacc[nj * 2], qf[kt], bl0);
                mma16816(sacc[nj * 2 + 1], qf[kt], bh1);
                mma16816(sacc[nj * 2 + 1], qf[kt], bl1);
            }
        }

        #pragma unroll
        for (int nt = 0; nt < 8; ++nt) {
            sacc[nt][0] *= 0.125f; sacc[nt][1] *= 0.125f;
            sacc[nt][2] *= 0.125f; sacc[nt][3] *= 0.125f;
        }
        if (j0 == qt) {
            #pragma unroll
            for (int nt = 0; nt < 8; ++nt) {
                const int jc = nt * 8 + cloc;
                if (jc > rloc)     sacc[nt][0] = -INFINITY;
                if (jc + 1 > rloc) sacc[nt][1] = -INFINITY;
                if (jc > rloc + 8)     sacc[nt][2] = -INFINITY;
                if (jc + 1 > rloc + 8) sacc[nt][3] = -INFINITY;
            }
        }
        float mx0 = -INFINITY, mx1 = -INFINITY;
        #pragma unroll
        for (int nt = 0; nt < 8; ++nt) {
            mx0 = fmaxf(mx0, fmaxf(sacc[nt][0], sacc[nt][1]));
            mx1 = fmaxf(mx1, fmaxf(sacc[nt][2], sacc[nt][3]));
        }
        mx0 = fmaxf(mx0, __shfl_xor_sync(0xffffffffu, mx0, 1));
        mx0 = fmaxf(mx0, __shfl_xor_sync(0xffffffffu, mx0, 2));
        mx1 = fmaxf(mx1, __shfl_xor_sync(0xffffffffu, mx1, 1));
        mx1 = fmaxf(mx1, __shfl_xor_sync(0xffffffffu, mx1, 2));
        const float mn0 = fmaxf(m_r[0], mx0), mn1 = fmaxf(m_r[1], mx1);
        const float al0 = __expf(m_r[0] - mn0), al1 = __expf(m_r[1] - mn1);
        m_r[0] = mn0; m_r[1] = mn1;

        float rs0 = 0.f, rs1 = 0.f;
        #pragma unroll
        for (int nt = 0; nt < 8; ++nt) {
            sacc[nt][0] = __expf(sacc[nt][0] - mn0); rs0 += sacc[nt][0];
            sacc[nt][1] = __expf(sacc[nt][1] - mn0); rs0 += sacc[nt][1];
            sacc[nt][2] = __expf(sacc[nt][2] - mn1); rs1 += sacc[nt][2];
            sacc[nt][3] = __expf(sacc[nt][3] - mn1); rs1 += sacc[nt][3];
        }
        rs0 += __shfl_xor_sync(0xffffffffu, rs0, 1);
        rs0 += __shfl_xor_sync(0xffffffffu, rs0, 2);
        rs1 += __shfl_xor_sync(0xffffffffu, rs1, 1);
        rs1 += __shfl_xor_sync(0xffffffffu, rs1, 2);
        l_r[0] = l_r[0] * al0 + rs0;
        l_r[1] = l_r[1] * al1 + rs1;
        #pragma unroll
        for (int nt = 0; nt < 8; ++nt) {
            oacc[nt][0] *= al0; oacc[nt][1] *= al0;
            oacc[nt][2] *= al1; oacc[nt][3] *= al1;
        }

        #pragma unroll
        for (int kt = 0; kt < 4; ++kt) {
            uint32_t ph[4];
            ph[0] = pack_h(sacc[2 * kt][0], sacc[2 * kt][1]);
            ph[1] = pack_h(sacc[2 * kt][2], sacc[2 * kt][3]);
            ph[2] = pack_h(sacc[2 * kt + 1][0], sacc[2 * kt + 1][1]);
            ph[3] = pack_h(sacc[2 * kt + 1][2], sacc[2 * kt + 1][3]);
            #pragma unroll
            for (int nj = 0; nj < 4; ++nj) {
                uint32_t v0, v1, v2, v3, w0, w1, w2, w3;
                const int off = kt * 16 * FST * 2 + nj * 32;
                ldsm4t(bVh + voffV + off, v0, v1, v2, v3);
                ldsm4t(bVl + voffV + off, w0, w1, w2, w3);
                uint32_t vh0[2] = { v0, v1 }, vh1[2] = { v2, v3 };
                uint32_t vl0[2] = { w0, w1 }, vl1[2] = { w2, w3 };
                mma16816(oacc[nj * 2], ph, vh0);
                mma16816(oacc[nj * 2], ph, vl0);
                mma16816(oacc[nj * 2 + 1], ph, vh1);
                mma16816(oacc[nj * 2 + 1], ph, vl1);
            }
        }
    }

    const float inv0 = 1.f / l_r[0], inv1 = 1.f / l_r[1];
    const int qrow = q0 + rloc;
    #pragma unroll
    for (int nt = 0; nt < 8; ++nt) {
        const int col = h * HD + nt * 8 + cloc;
        const float v0 = oacc[nt][0] * inv0, v1 = oacc[nt][1] * inv0;
        const float v2 = oacc[nt][2] * inv1, v3 = oacc[nt][3] * inv1;
        const size_t r0 = ((size_t)b * SEQ + qrow) * EMB + col;
        const size_t r1 = ((size_t)b * SEQ + qrow + 8) * EMB + col;
        *(uint32_t*)&attn[r0] = pack_h(v0, v1);
        *(uint32_t*)&attn[r1] = pack_h(v2, v3);
    }
}

// ---------------------------------------------------------------------------
extern "C" void kernel_launch(void* const* d_in, const int* in_sizes, int n_in,
                              void* d_out, int out_size)
{
    const float* x    = (const float*)d_in[0];
    const float* Wqkv = (const float*)d_in[1];
    const float* bqkv = (const float*)d_in[2];
    const float* Wout = (const float*)d_in[3];
    const float* bout = (const float*)d_in[4];
    float* out = (float*)d_out;

    __half *xh, *w1h, *w1l, *w2h, *w2l, *qkvh, *qkvl, *ah;
    cudaGetSymbolAddress((void**)&xh, g_xh);
    cudaGetSymbolAddress((void**)&w1h, g_w1h);
    cudaGetSymbolAddress((void**)&w1l, g_w1l);
    cudaGetSymbolAddress((void**)&w2h, g_w2h);
    cudaGetSymbolAddress((void**)&w2l, g_w2l);
    cudaGetSymbolAddress((void**)&qkvh, g_qkvh);
    cudaGetSymbolAddress((void**)&qkvl, g_qkvl);
    cudaGetSymbolAddress((void**)&ah, g_ah);

    cudaFuncSetAttribute(flash_mma,
                         cudaFuncAttributeMaxDynamicSharedMemorySize, FLASH_SMEM);
    cudaFuncSetAttribute(mma_gemm_bias<true>,
                         cudaFuncAttributeMaxDynamicSharedMemorySize, GEMM_SMEM);
    cudaFuncSetAttribute(mma_gemm_bias<false>,
                         cudaFuncAttributeMaxDynamicSharedMemorySize, GEMM_SMEM);

    const int nx  = BSZ * SEQ * EMB;
    const int nw1 = 3 * EMB * EMB;
    const int nw2 = EMB * EMB;

    // 0) conversions
    conv_kernel<<<nx / 4 / 256, 256>>>((const float4*)x, (uint2*)xh, nx / 4);
    split_kernel<<<nw1 / 4 / 256, 256>>>((const float4*)Wqkv, (uint2*)w1h, (uint2*)w1l, nw1 / 4);
    split_kernel<<<nw2 / 4 / 256, 256>>>((const float4*)Wout, (uint2*)w2h, (uint2*)w2l, nw2 / 4);

    // 1) qkv = x @ Wqkv^T + bqkv  -> fp16 hi/lo
    mma_gemm_bias<true><<<dim3(3 * EMB / 128, BSZ * SEQ / 128), 256, GEMM_SMEM>>>(
        xh, w1h, w1l, bqkv, nullptr, qkvh, qkvl, BSZ * SEQ, 3 * EMB, EMB);

    // 2) causal flash attention -> attn fp16
    flash_mma<<<dim3(SEQ / 64, NH, BSZ), 128, FLASH_SMEM>>>(qkvh, qkvl, ah);

    // 3) out = attn @ Wout^T + bout  (fp32 out)
    mma_gemm_bias<false><<<dim3(EMB / 128, BSZ * SEQ / 128), 256, GEMM_SMEM>>>(
        ah, w2h, w2l, bout, out, nullptr, nullptr, BSZ * SEQ, EMB, EMB);
}

// round 7
// speedup vs baseline: 3.7053x; 1.0218x over previous
#include <cuda_runtime.h>
#include <cuda_fp16.h>
#include <math.h>
#include <stdint.h>

#define BSZ 2
#define SEQ 2048
#define EMB 1024
#define NH  16
#define HD  64

// ---------------------------------------------------------------------------
// Scratch (__device__ globals)
// ---------------------------------------------------------------------------
__device__ __half g_xh[(size_t)BSZ * SEQ * EMB];
__device__ __half g_w1h[(size_t)3 * EMB * EMB];
__device__ __half g_w1l[(size_t)3 * EMB * EMB];
__device__ __half g_w2h[(size_t)EMB * EMB];
__device__ __half g_w2l[(size_t)EMB * EMB];
__device__ __half g_qkvh[(size_t)BSZ * SEQ * 3 * EMB];
__device__ __half g_qkvl[(size_t)BSZ * SEQ * 3 * EMB];
__device__ __half g_ah[(size_t)BSZ * SEQ * EMB];

// ---------------------------------------------------------------------------
// fp32 -> fp16 convert / split
// ---------------------------------------------------------------------------
__global__ __launch_bounds__(256) void conv_kernel(
    const float4* __restrict__ in, uint2* __restrict__ hi, int n4)
{
    int i = blockIdx.x * blockDim.x + threadIdx.x;
    if (i >= n4) return;
    float4 v = in[i];
    __half2 a(__float2half_rn(v.x), __float2half_rn(v.y));
    __half2 b(__float2half_rn(v.z), __float2half_rn(v.w));
    uint2 H;
    H.x = *reinterpret_cast<uint32_t*>(&a);
    H.y = *reinterpret_cast<uint32_t*>(&b);
    hi[i] = H;
}

__global__ __launch_bounds__(256) void split_kernel(
    const float4* __restrict__ in, uint2* __restrict__ hi,
    uint2* __restrict__ lo, int n4)
{
    int i = blockIdx.x * blockDim.x + threadIdx.x;
    if (i >= n4) return;
    float4 v = in[i];
    __half h0 = __float2half_rn(v.x), h1 = __float2half_rn(v.y);
    __half h2 = __float2half_rn(v.z), h3 = __float2half_rn(v.w);
    __half l0 = __float2half_rn(v.x - __half2float(h0));
    __half l1 = __float2half_rn(v.y - __half2float(h1));
    __half l2 = __float2half_rn(v.z - __half2float(h2));
    __half l3 = __float2half_rn(v.w - __half2float(h3));
    __half2 hA(h0, h1), hB(h2, h3), lA(l0, l1), lB(l2, l3);
    uint2 H, L;
    H.x = *reinterpret_cast<uint32_t*>(&hA); H.y = *reinterpret_cast<uint32_t*>(&hB);
    L.x = *reinterpret_cast<uint32_t*>(&lA); L.y = *reinterpret_cast<uint32_t*>(&lB);
    hi[i] = H; lo[i] = L;
}

// ---------------------------------------------------------------------------
// MMA / cp.async helpers (fp16)
// ---------------------------------------------------------------------------
__device__ __forceinline__ void ldsm4(uint32_t a, uint32_t& r0, uint32_t& r1,
                                      uint32_t& r2, uint32_t& r3)
{
    asm volatile("ldmatrix.sync.aligned.m8n8.x4.shared.b16 {%0,%1,%2,%3}, [%4];\n"
                 : "=r"(r0), "=r"(r1), "=r"(r2), "=r"(r3) : "r"(a));
}
__device__ __forceinline__ void ldsm4t(uint32_t a, uint32_t& r0, uint32_t& r1,
                                       uint32_t& r2, uint32_t& r3)
{
    asm volatile("ldmatrix.sync.aligned.m8n8.x4.trans.shared.b16 {%0,%1,%2,%3}, [%4];\n"
                 : "=r"(r0), "=r"(r1), "=r"(r2), "=r"(r3) : "r"(a));
}
__device__ __forceinline__ void mma16816(float* d, const uint32_t* a, const uint32_t* b)
{
    asm volatile("mma.sync.aligned.m16n8k16.row.col.f32.f16.f16.f32 "
                 "{%0,%1,%2,%3}, {%4,%5,%6,%7}, {%8,%9}, {%0,%1,%2,%3};\n"
                 : "+f"(d[0]), "+f"(d[1]), "+f"(d[2]), "+f"(d[3])
                 : "r"(a[0]), "r"(a[1]), "r"(a[2]), "r"(a[3]), "r"(b[0]), "r"(b[1]));
}
__device__ __forceinline__ uint32_t pack_h(float a, float b)
{
    __half2 p(__float2half_rn(a), __float2half_rn(b));
    return *reinterpret_cast<uint32_t*>(&p);
}
__device__ __forceinline__ uint32_t pack_l(float a, float b)
{
    __half ha = __float2half_rn(a), hb = __float2half_rn(b);
    __half2 p(__float2half_rn(a - __half2float(ha)),
              __float2half_rn(b - __half2float(hb)));
    return *reinterpret_cast<uint32_t*>(&p);
}
__device__ __forceinline__ void cp16(uint32_t saddr, const void* gaddr)
{
    asm volatile("cp.async.cg.shared.global [%0], [%1], 16;" :: "r"(saddr), "l"(gaddr));
}
#define CP_COMMIT() asm volatile("cp.async.commit_group;" ::: "memory")
#define CP_WAIT1()  asm volatile("cp.async.wait_group 1;" ::: "memory")
#define CP_WAIT0()  asm volatile("cp.async.wait_group 0;" ::: "memory")

// ---------------------------------------------------------------------------
// fp16 2-term GEMM:  C = A·B^T + bias ≈ Ah·Bh^T + Ah·Bl^T
// CTA 128x128, warp 64x32, K-chunks of 64 (2-stage cp.async), 2 CTAs/SM.
// Stride-72 rows: conflict-free for this ldmatrix pattern (proven in flash).
// SKIP_LO_N0: lo-epilogue suppressed for output cols < 1024 (Q third —
// its lo is never consumed by flash).
// ---------------------------------------------------------------------------
#define SAST 72
#define GARR_B  (128 * SAST * 2)        // 18432 B per array
#define GSTG_B  (3 * GARR_B)            // 55296 B per stage (Ah, Bh, Bl)
#define GEMM_SMEM (2 * GSTG_B)          // 110592

template<bool SPLIT_OUT>
__global__ __launch_bounds__(256, 2) void mma_gemm_bias(
    const __half* __restrict__ Ah,
    const __half* __restrict__ Bhi, const __half* __restrict__ Blo,
    const float* __restrict__ bias, float* __restrict__ Cf,
    __half* __restrict__ Chi, __half* __restrict__ Clo,
    int M, int N, int K)
{
    extern __shared__ __align__(16) unsigned char gsm[];
    const uint32_t sb = (uint32_t)__cvta_generic_to_shared(gsm);

    const int tid = threadIdx.x, lane = tid & 31, wid = tid >> 5;
    const int wm = (wid >> 2) * 64;
    const int wn = (wid & 3) * 32;
    const int m0 = blockIdx.y * 128, n0 = blockIdx.x * 128;

    const int lrow = tid >> 1;
    const int lcol = (tid & 1) * 16;
    const uint32_t so = (uint32_t)(lrow * SAST + lcol) * 2;
    const __half* gAh = Ah  + (size_t)(m0 + lrow) * K + lcol;
    const __half* gBh = Bhi + (size_t)(n0 + lrow) * K + lcol;
    const __half* gBl = Blo + (size_t)(n0 + lrow) * K + lcol;

    const int aoff = ((wm + (lane & 15)) * SAST + (lane >> 4) * 8) * 2;
    const int boff = ((wn + (lane & 7) + ((lane >> 4) & 1) * 8) * SAST
                      + ((lane >> 3) & 1) * 8) * 2;

    float acc[4][4][4];
    #pragma unroll
    for (int i = 0; i < 4; ++i)
        #pragma unroll
        for (int j = 0; j < 4; ++j)
            acc[i][j][0] = acc[i][j][1] = acc[i][j][2] = acc[i][j][3] = 0.f;

    const int NCH = K / 64;   // 16

    // stage loader: 64 k-cols per chunk; each thread covers [lcol,lcol+16) and
    // [lcol+32,lcol+48) of its row for each of the 3 arrays.
    auto load_stage = [&](int c, int st) {
        const int kc = c * 64;
        const uint32_t base = sb + st * GSTG_B + so;
        cp16(base,                     gAh + kc);
        cp16(base + 16,                gAh + kc + 8);
        cp16(base + 64,                gAh + kc + 32);
        cp16(base + 80,                gAh + kc + 40);
        cp16(base + GARR_B,            gBh + kc);
        cp16(base + GARR_B + 16,       gBh + kc + 8);
        cp16(base + GARR_B + 64,       gBh + kc + 32);
        cp16(base + GARR_B + 80,       gBh + kc + 40);
        cp16(base + 2 * GARR_B,        gBl + kc);
        cp16(base + 2 * GARR_B + 16,   gBl + kc + 8);
        cp16(base + 2 * GARR_B + 64,   gBl + kc + 32);
        cp16(base + 2 * GARR_B + 80,   gBl + kc + 40);
        CP_COMMIT();
    };

    load_stage(0, 0);
    load_stage(1, 1);

    for (int c = 0; c < NCH; ++c) {
        if (c == NCH - 1) { CP_WAIT0(); } else { CP_WAIT1(); }
        __syncthreads();

        const int st = c & 1;
        const uint32_t bAh = sb + st * GSTG_B;
        const uint32_t bBh = bAh + GARR_B;
        const uint32_t bBl = bAh + 2 * GARR_B;

        #pragma unroll
        for (int ks = 0; ks < 4; ++ks) {
            const int kb = ks * 32;   // 16 fp16 = 32 bytes
            uint32_t a[4][4], bh[4][2], bl[4][2];
            #pragma unroll
            for (int mi = 0; mi < 4; ++mi) {
                const int mo = mi * 16 * SAST * 2 + kb;
                ldsm4(bAh + aoff + mo, a[mi][0], a[mi][1], a[mi][2], a[mi][3]);
            }
            #pragma unroll
            for (int nj = 0; nj < 2; ++nj) {
                const int no = nj * 16 * SAST * 2 + kb;
                uint32_t t0, t1, t2, t3;
                ldsm4(bBh + boff + no, t0, t1, t2, t3);
                bh[nj * 2][0] = t0; bh[nj * 2][1] = t1;
                bh[nj * 2 + 1][0] = t2; bh[nj * 2 + 1][1] = t3;
                ldsm4(bBl + boff + no, t0, t1, t2, t3);
                bl[nj * 2][0] = t0; bl[nj * 2][1] = t1;
                bl[nj * 2 + 1][0] = t2; bl[nj * 2 + 1][1] = t3;
            }
            #pragma unroll
            for (int mi = 0; mi < 4; ++mi)
                #pragma unroll
                for (int ni = 0; ni < 4; ++ni) {
                    mma16816(acc[mi][ni], a[mi], bh[ni]);
                    mma16816(acc[mi][ni], a[mi], bl[ni]);
                }
        }
        __syncthreads();
        if (c + 2 < NCH) load_stage(c + 2, st);
    }

    const int rbase = m0 + wm + (lane >> 2);
    const int cbase = n0 + wn + (lane & 3) * 2;
    const bool write_lo = SPLIT_OUT && (n0 >= 1024);   // K,V thirds only
    #pragma unroll
    for (int mi = 0; mi < 4; ++mi) {
        const int r = rbase + mi * 16;
        #pragma unroll
        for (int ni = 0; ni < 4; ++ni) {
            const int c = cbase + ni * 8;
            const float b0 = bias[c], b1 = bias[c + 1];
            const float v0 = acc[mi][ni][0] + b0, v1 = acc[mi][ni][1] + b1;
            const float v2 = acc[mi][ni][2] + b0, v3 = acc[mi][ni][3] + b1;
            if (SPLIT_OUT) {
                *(uint32_t*)&Chi[(size_t)r * N + c]       = pack_h(v0, v1);
                *(uint32_t*)&Chi[(size_t)(r + 8) * N + c] = pack_h(v2, v3);
                if (write_lo) {
                    *(uint32_t*)&Clo[(size_t)r * N + c]       = pack_l(v0, v1);
                    *(uint32_t*)&Clo[(size_t)(r + 8) * N + c] = pack_l(v2, v3);
                }
            } else {
                float2 o0 = { v0, v1 }, o1 = { v2, v3 };
                *(float2*)&Cf[(size_t)r * N + c] = o0;
                *(float2*)&Cf[(size_t)(r + 8) * N + c] = o1;
            }
        }
    }
}

// ---------------------------------------------------------------------------
// fp16 2-term flash attention (causal, no-transpose head reshape).
// qt reversed so longest (largest-qt) tiles schedule first -> better tail.
// ---------------------------------------------------------------------------
#define FST 72
#define FLASH_SMEM (5 * 64 * FST * 2)

__global__ __launch_bounds__(128) void flash_mma(
    const __half* __restrict__ qkvh, const __half* __restrict__ qkvl,
    __half* __restrict__ attn)
{
    extern __shared__ __half fsm[];
    __half* sQ  = fsm;
    __half* sKh = fsm + 1 * 64 * FST;
    __half* sKl = fsm + 2 * 64 * FST;
    __half* sVh = fsm + 3 * 64 * FST;
    __half* sVl = fsm + 4 * 64 * FST;

    const int b = blockIdx.z, h = blockIdx.y;
    const int qt = gridDim.x - 1 - blockIdx.x;    // long tiles first
    const int tid = threadIdx.x, lane = tid & 31, wid = tid >> 5;
    const size_t bbase = (size_t)b * SEQ * 3 * EMB;
    const int hbase = h * SEQ * HD;
    const int q0 = qt * 64;

    #pragma unroll
    for (int i = 0; i < 4; ++i) {
        const int id = tid + 128 * i;
        const int r = id >> 3, c = (id & 7) * 8;
        const int f = hbase + (q0 + r) * HD + c;
        const size_t ga = bbase + (size_t)(f >> 10) * 3072 + (f & 1023);
        *(uint4*)&sQ[r * FST + c] = *(const uint4*)&qkvh[ga];
    }
    __syncthreads();

    const uint32_t bQ  = (uint32_t)__cvta_generic_to_shared(sQ);
    const uint32_t bKh = (uint32_t)__cvta_generic_to_shared(sKh);
    const uint32_t bKl = (uint32_t)__cvta_generic_to_shared(sKl);
    const uint32_t bVh = (uint32_t)__cvta_generic_to_shared(sVh);
    const uint32_t bVl = (uint32_t)__cvta_generic_to_shared(sVl);

    const int aoff = ((wid * 16 + (lane & 15)) * FST + (lane >> 4) * 8) * 2;
    uint32_t qf[4][4];
    #pragma unroll
    for (int kt = 0; kt < 4; ++kt)
        ldsm4(bQ + aoff + kt * 32, qf[kt][0], qf[kt][1], qf[kt][2], qf[kt][3]);

    const int boffK = (((lane & 7) + ((lane >> 4) & 1) * 8) * FST + ((lane >> 3) & 1) * 8) * 2;
    const int voffV = (((lane & 7) + ((lane >> 3) & 1) * 8) * FST + (lane >> 4) * 8) * 2;

    float m_r[2] = { -INFINITY, -INFINITY };
    float l_r[2] = { 0.f, 0.f };
    float oacc[8][4];
    #pragma unroll
    for (int nt = 0; nt < 8; ++nt)
        oacc[nt][0] = oacc[nt][1] = oacc[nt][2] = oacc[nt][3] = 0.f;

    const int rloc = wid * 16 + (lane >> 2);
    const int cloc = 2 * (lane & 3);

    for (int j0 = 0; j0 <= qt; ++j0) {
        __syncthreads();
        #pragma unroll
        for (int i = 0; i < 4; ++i) {
            const int id = tid + 128 * i;
            const int r = id >> 3, c = (id & 7) * 8;
            const int f = hbase + (j0 * 64 + r) * HD + c;
            const size_t ga = bbase + (size_t)(f >> 10) * 3072 + (f & 1023);
            *(uint4*)&sKh[r * FST + c] = *(const uint4*)&qkvh[ga + 1024];
            *(uint4*)&sKl[r * FST + c] = *(const uint4*)&qkvl[ga + 1024];
            *(uint4*)&sVh[r * FST + c] = *(const uint4*)&qkvh[ga + 2048];
            *(uint4*)&sVl[r * FST + c] = *(const uint4*)&qkvl[ga + 2048];
        }
        __syncthreads();

        float sacc[8][4];
        #pragma unroll
        for (int nt = 0; nt < 8; ++nt)
            sacc[nt][0] = sacc[nt][1] = sacc[nt][2] = sacc[nt][3] = 0.f;

        #pragma unroll
        for (int kt = 0; kt < 4; ++kt) {
            #pragma unroll
            for (int nj = 0; nj < 4; ++nj) {
                uint32_t h0, h1, h2, h3, l0, l1, l2, l3;
                const int off = nj * 16 * FST * 2 + kt * 32;
                ldsm4(bKh + boffK + off, h0, h1, h2, h3);
                ldsm4(bKl + boffK + off, l0, l1, l2, l3);
                uint32_t bh0[2] = { h0, h1 }, bh1[2] = { h2, h3 };
                uint32_t bl0[2] = { l0, l1 }, bl1[2] = { l2, l3 };
                mma16816(sacc[nj * 2], qf[kt], bh0);
                mma16816(sacc[nj * 2], qf[kt], bl0);
                mma16816(sacc[nj * 2 + 1], qf[kt], bh1);
                mma16816(sacc[nj * 2 + 1], qf[kt], bl1);
            }
        }

        #pragma unroll
        for (int nt = 0; nt < 8; ++nt) {
            sacc[nt][0] *= 0.125f; sacc[nt][1] *= 0.125f;
            sacc[nt][2] *= 0.125f; sacc[nt][3] *= 0.125f;
        }
        if (j0 == qt) {
            #pragma unroll
            for (int nt = 0; nt < 8; ++nt) {
                const int jc = nt * 8 + cloc;
                if (jc > rloc)     sacc[nt][0] = -INFINITY;
                if (jc + 1 > rloc) sacc[nt][1] = -INFINITY;
                if (jc > rloc + 8)     sacc[nt][2] = -INFINITY;
                if (jc + 1 > rloc + 8) sacc[nt][3] = -INFINITY;
            }
        }
        float mx0 = -INFINITY, mx1 = -INFINITY;
        #pragma unroll
        for (int nt = 0; nt < 8; ++nt) {
            mx0 = fmaxf(mx0, fmaxf(sacc[nt][0], sacc[nt][1]));
            mx1 = fmaxf(mx1, fmaxf(sacc[nt][2], sacc[nt][3]));
        }
        mx0 = fmaxf(mx0, __shfl_xor_sync(0xffffffffu, mx0, 1));
        mx0 = fmaxf(mx0, __shfl_xor_sync(0xffffffffu, mx0, 2));
        mx1 = fmaxf(mx1, __shfl_xor_sync(0xffffffffu, mx1, 1));
        mx1 = fmaxf(mx1, __shfl_xor_sync(0xffffffffu, mx1, 2));
        const float mn0 = fmaxf(m_r[0], mx0), mn1 = fmaxf(m_r[1], mx1);
        const float al0 = __expf(m_r[0] - mn0), al1 = __expf(m_r[1] - mn1);
        m_r[0] = mn0; m_r[1] = mn1;

        float rs0 = 0.f, rs1 = 0.f;
        #pragma unroll
        for (int nt = 0; nt < 8; ++nt) {
            sacc[nt][0] = __expf(sacc[nt][0] - mn0); rs0 += sacc[nt][0];
            sacc[nt][1] = __expf(sacc[nt][1] - mn0); rs0 += sacc[nt][1];
            sacc[nt][2] = __expf(sacc[nt][2] - mn1); rs1 += sacc[nt][2];
            sacc[nt][3] = __expf(sacc[nt][3] - mn1); rs1 += sacc[nt][3];
        }
        rs0 += __shfl_xor_sync(0xffffffffu, rs0, 1);
        rs0 += __shfl_xor_sync(0xffffffffu, rs0, 2);
        rs1 += __shfl_xor_sync(0xffffffffu, rs1, 1);
        rs1 += __shfl_xor_sync(0xffffffffu, rs1, 2);
        l_r[0] = l_r[0] * al0 + rs0;
        l_r[1] = l_r[1] * al1 + rs1;
        #pragma unroll
        for (int nt = 0; nt < 8; ++nt) {
            oacc[nt][0] *= al0; oacc[nt][1] *= al0;
            oacc[nt][2] *= al1; oacc[nt][3] *= al1;
        }

        #pragma unroll
        for (int kt = 0; kt < 4; ++kt) {
            uint32_t ph[4];
            ph[0] = pack_h(sacc[2 * kt][0], sacc[2 * kt][1]);
            ph[1] = pack_h(sacc[2 * kt][2], sacc[2 * kt][3]);
            ph[2] = pack_h(sacc[2 * kt + 1][0], sacc[2 * kt + 1][1]);
            ph[3] = pack_h(sacc[2 * kt + 1][2], sacc[2 * kt + 1][3]);
            #pragma unroll
            for (int nj = 0; nj < 4; ++nj) {
                uint32_t v0, v1, v2, v3, w0, w1, w2, w3;
                const int off = kt * 16 * FST * 2 + nj * 32;
                ldsm4t(bVh + voffV + off, v0, v1, v2, v3);
                ldsm4t(bVl + voffV + off, w0, w1, w2, w3);
                uint32_t vh0[2] = { v0, v1 }, vh1[2] = { v2, v3 };
                uint32_t vl0[2] = { w0, w1 }, vl1[2] = { w2, w3 };
                mma16816(oacc[nj * 2], ph, vh0);
                mma16816(oacc[nj * 2], ph, vl0);
                mma16816(oacc[nj * 2 + 1], ph, vh1);
                mma16816(oacc[nj * 2 + 1], ph, vl1);
            }
        }
    }

    const float inv0 = 1.f / l_r[0], inv1 = 1.f / l_r[1];
    const int qrow = q0 + rloc;
    #pragma unroll
    for (int nt = 0; nt < 8; ++nt) {
        const int col = h * HD + nt * 8 + cloc;
        const float v0 = oacc[nt][0] * inv0, v1 = oacc[nt][1] * inv0;
        const float v2 = oacc[nt][2] * inv1, v3 = oacc[nt][3] * inv1;
        const size_t r0 = ((size_t)b * SEQ + qrow) * EMB + col;
        const size_t r1 = ((size_t)b * SEQ + qrow + 8) * EMB + col;
        *(uint32_t*)&attn[r0] = pack_h(v0, v1);
        *(uint32_t*)&attn[r1] = pack_h(v2, v3);
    }
}

// ---------------------------------------------------------------------------
extern "C" void kernel_launch(void* const* d_in, const int* in_sizes, int n_in,
                              void* d_out, int out_size)
{
    const float* x    = (const float*)d_in[0];
    const float* Wqkv = (const float*)d_in[1];
    const float* bqkv = (const float*)d_in[2];
    const float* Wout = (const float*)d_in[3];
    const float* bout = (const float*)d_in[4];
    float* out = (float*)d_out;

    __half *xh, *w1h, *w1l, *w2h, *w2l, *qkvh, *qkvl, *ah;
    cudaGetSymbolAddress((void**)&xh, g_xh);
    cudaGetSymbolAddress((void**)&w1h, g_w1h);
    cudaGetSymbolAddress((void**)&w1l, g_w1l);
    cudaGetSymbolAddress((void**)&w2h, g_w2h);
    cudaGetSymbolAddress((void**)&w2l, g_w2l);
    cudaGetSymbolAddress((void**)&qkvh, g_qkvh);
    cudaGetSymbolAddress((void**)&qkvl, g_qkvl);
    cudaGetSymbolAddress((void**)&ah, g_ah);

    cudaFuncSetAttribute(flash_mma,
                         cudaFuncAttributeMaxDynamicSharedMemorySize, FLASH_SMEM);
    cudaFuncSetAttribute(mma_gemm_bias<true>,
                         cudaFuncAttributeMaxDynamicSharedMemorySize, GEMM_SMEM);
    cudaFuncSetAttribute(mma_gemm_bias<false>,
                         cudaFuncAttributeMaxDynamicSharedMemorySize, GEMM_SMEM);

    const int nx  = BSZ * SEQ * EMB;
    const int nw1 = 3 * EMB * EMB;
    const int nw2 = EMB * EMB;

    // 0) conversions
    conv_kernel<<<nx / 4 / 256, 256>>>((const float4*)x, (uint2*)xh, nx / 4);
    split_kernel<<<nw1 / 4 / 256, 256>>>((const float4*)Wqkv, (uint2*)w1h, (uint2*)w1l, nw1 / 4);
    split_kernel<<<nw2 / 4 / 256, 256>>>((const float4*)Wout, (uint2*)w2h, (uint2*)w2l, nw2 / 4);

    // 1) qkv = x @ Wqkv^T + bqkv  -> fp16 hi/lo (lo skipped for Q third)
    mma_gemm_bias<true><<<dim3(3 * EMB / 128, BSZ * SEQ / 128), 256, GEMM_SMEM>>>(
        xh, w1h, w1l, bqkv, nullptr, qkvh, qkvl, BSZ * SEQ, 3 * EMB, EMB);

    // 2) causal flash attention -> attn fp16
    flash_mma<<<dim3(SEQ / 64, NH, BSZ), 128, FLASH_SMEM>>>(qkvh, qkvl, ah);

    // 3) out = attn @ Wout^T + bout  (fp32 out)
    mma_gemm_bias<false><<<dim3(EMB / 128, BSZ * SEQ / 128), 256, GEMM_SMEM>>>(
        ah, w2h, w2l, bout, out, nullptr, nullptr, BSZ * SEQ, EMB, EMB);
}

// round 8
// speedup vs baseline: 3.8955x; 1.0513x over previous
#include <cuda_runtime.h>
#include <cuda_fp16.h>
#include <math.h>
#include <stdint.h>

#define BSZ 2
#define SEQ 2048
#define EMB 1024
#define NH  16
#define HD  64

// ---------------------------------------------------------------------------
// Scratch (__device__ globals)
// ---------------------------------------------------------------------------
__device__ __half g_xh[(size_t)BSZ * SEQ * EMB];
__device__ __half g_w1h[(size_t)3 * EMB * EMB];
__device__ __half g_w1l[(size_t)3 * EMB * EMB];     // lo pre-scaled by 2^11
__device__ __half g_w2h[(size_t)EMB * EMB];
__device__ __half g_w2l[(size_t)EMB * EMB];         // lo pre-scaled by 2^11
__device__ __half g_qkvh[(size_t)BSZ * SEQ * 3 * EMB];
__device__ __half g_ah[(size_t)BSZ * SEQ * EMB];

#define LO_SCALE   2048.0f
#define LO_UNSCALE 4.8828125e-4f   // 2^-11

// ---------------------------------------------------------------------------
// fp32 -> fp16 convert / split (lo scaled by 2^11)
// ---------------------------------------------------------------------------
__global__ __launch_bounds__(256) void conv_kernel(
    const float4* __restrict__ in, uint2* __restrict__ hi, int n4)
{
    int i = blockIdx.x * blockDim.x + threadIdx.x;
    if (i >= n4) return;
    float4 v = in[i];
    __half2 a(__float2half_rn(v.x), __float2half_rn(v.y));
    __half2 b(__float2half_rn(v.z), __float2half_rn(v.w));
    uint2 H;
    H.x = *reinterpret_cast<uint32_t*>(&a);
    H.y = *reinterpret_cast<uint32_t*>(&b);
    hi[i] = H;
}

__global__ __launch_bounds__(256) void split_kernel(
    const float4* __restrict__ in, uint2* __restrict__ hi,
    uint2* __restrict__ lo, int n4)
{
    int i = blockIdx.x * blockDim.x + threadIdx.x;
    if (i >= n4) return;
    float4 v = in[i];
    __half h0 = __float2half_rn(v.x), h1 = __float2half_rn(v.y);
    __half h2 = __float2half_rn(v.z), h3 = __float2half_rn(v.w);
    __half l0 = __float2half_rn((v.x - __half2float(h0)) * LO_SCALE);
    __half l1 = __float2half_rn((v.y - __half2float(h1)) * LO_SCALE);
    __half l2 = __float2half_rn((v.z - __half2float(h2)) * LO_SCALE);
    __half l3 = __float2half_rn((v.w - __half2float(h3)) * LO_SCALE);
    __half2 hA(h0, h1), hB(h2, h3), lA(l0, l1), lB(l2, l3);
    uint2 H, L;
    H.x = *reinterpret_cast<uint32_t*>(&hA); H.y = *reinterpret_cast<uint32_t*>(&hB);
    L.x = *reinterpret_cast<uint32_t*>(&lA); L.y = *reinterpret_cast<uint32_t*>(&lB);
    hi[i] = H; lo[i] = L;
}

// ---------------------------------------------------------------------------
// MMA / cp.async helpers
// ---------------------------------------------------------------------------
__device__ __forceinline__ void ldsm4(uint32_t a, uint32_t& r0, uint32_t& r1,
                                      uint32_t& r2, uint32_t& r3)
{
    asm volatile("ldmatrix.sync.aligned.m8n8.x4.shared.b16 {%0,%1,%2,%3}, [%4];\n"
                 : "=r"(r0), "=r"(r1), "=r"(r2), "=r"(r3) : "r"(a));
}
__device__ __forceinline__ void ldsm4t(uint32_t a, uint32_t& r0, uint32_t& r1,
                                       uint32_t& r2, uint32_t& r3)
{
    asm volatile("ldmatrix.sync.aligned.m8n8.x4.trans.shared.b16 {%0,%1,%2,%3}, [%4];\n"
                 : "=r"(r0), "=r"(r1), "=r"(r2), "=r"(r3) : "r"(a));
}
__device__ __forceinline__ void mma16816(float* d, const uint32_t* a, const uint32_t* b)
{
    asm volatile("mma.sync.aligned.m16n8k16.row.col.f32.f16.f16.f32 "
                 "{%0,%1,%2,%3}, {%4,%5,%6,%7}, {%8,%9}, {%0,%1,%2,%3};\n"
                 : "+f"(d[0]), "+f"(d[1]), "+f"(d[2]), "+f"(d[3])
                 : "r"(a[0]), "r"(a[1]), "r"(a[2]), "r"(a[3]), "r"(b[0]), "r"(b[1]));
}
// fp16-accumulator MMA (potentially double-rate on the legacy path)
__device__ __forceinline__ void mma16816h(uint32_t* d, const uint32_t* a, const uint32_t* b)
{
    asm volatile("mma.sync.aligned.m16n8k16.row.col.f16.f16.f16.f16 "
                 "{%0,%1}, {%2,%3,%4,%5}, {%6,%7}, {%0,%1};\n"
                 : "+r"(d[0]), "+r"(d[1])
                 : "r"(a[0]), "r"(a[1]), "r"(a[2]), "r"(a[3]), "r"(b[0]), "r"(b[1]));
}
__device__ __forceinline__ uint32_t pack_h(float a, float b)
{
    __half2 p(__float2half_rn(a), __float2half_rn(b));
    return *reinterpret_cast<uint32_t*>(&p);
}
__device__ __forceinline__ void cp16(uint32_t saddr, const void* gaddr)
{
    asm volatile("cp.async.cg.shared.global [%0], [%1], 16;" :: "r"(saddr), "l"(gaddr));
}
#define CP_COMMIT() asm volatile("cp.async.commit_group;" ::: "memory")
#define CP_WAIT1()  asm volatile("cp.async.wait_group 1;" ::: "memory")
#define CP_WAIT0()  asm volatile("cp.async.wait_group 0;" ::: "memory")

// ---------------------------------------------------------------------------
// fp16 GEMM:  C = A·B^T + bias ≈ Ah·Bh^T (fp32 acc) + 2^-11 · Ah·Bl'^T (fp16 acc)
// where Bl' = (B - Bh)·2^11.  CTA 128x128, warp 64x32, K-chunks of 64.
// ---------------------------------------------------------------------------
#define SAST 72
#define GARR_B  (128 * SAST * 2)
#define GSTG_B  (3 * GARR_B)
#define GEMM_SMEM (2 * GSTG_B)          // 110592

template<bool HALF_OUT>
__global__ __launch_bounds__(256) void mma_gemm_bias(
    const __half* __restrict__ Ah,
    const __half* __restrict__ Bhi, const __half* __restrict__ Blo,
    const float* __restrict__ bias, float* __restrict__ Cf,
    __half* __restrict__ Ch,
    int M, int N, int K)
{
    extern __shared__ __align__(16) unsigned char gsm[];
    const uint32_t sb = (uint32_t)__cvta_generic_to_shared(gsm);

    const int tid = threadIdx.x, lane = tid & 31, wid = tid >> 5;
    const int wm = (wid >> 2) * 64;
    const int wn = (wid & 3) * 32;
    const int m0 = blockIdx.y * 128, n0 = blockIdx.x * 128;

    const int lrow = tid >> 1;
    const int lcol = (tid & 1) * 16;
    const uint32_t so = (uint32_t)(lrow * SAST + lcol) * 2;
    const __half* gAh = Ah  + (size_t)(m0 + lrow) * K + lcol;
    const __half* gBh = Bhi + (size_t)(n0 + lrow) * K + lcol;
    const __half* gBl = Blo + (size_t)(n0 + lrow) * K + lcol;

    const int aoff = ((wm + (lane & 15)) * SAST + (lane >> 4) * 8) * 2;
    const int boff = ((wn + (lane & 7) + ((lane >> 4) & 1) * 8) * SAST
                      + ((lane >> 3) & 1) * 8) * 2;

    float acc[4][4][4];
    uint32_t accl[4][4][2];
    #pragma unroll
    for (int i = 0; i < 4; ++i)
        #pragma unroll
        for (int j = 0; j < 4; ++j) {
            acc[i][j][0] = acc[i][j][1] = acc[i][j][2] = acc[i][j][3] = 0.f;
            accl[i][j][0] = accl[i][j][1] = 0u;
        }

    const int NCH = K / 64;

    auto load_stage = [&](int c, int st) {
        const int kc = c * 64;
        const uint32_t base = sb + st * GSTG_B + so;
        cp16(base,                     gAh + kc);
        cp16(base + 16,                gAh + kc + 8);
        cp16(base + 64,                gAh + kc + 32);
        cp16(base + 80,                gAh + kc + 40);
        cp16(base + GARR_B,            gBh + kc);
        cp16(base + GARR_B + 16,       gBh + kc + 8);
        cp16(base + GARR_B + 64,       gBh + kc + 32);
        cp16(base + GARR_B + 80,       gBh + kc + 40);
        cp16(base + 2 * GARR_B,        gBl + kc);
        cp16(base + 2 * GARR_B + 16,   gBl + kc + 8);
        cp16(base + 2 * GARR_B + 64,   gBl + kc + 32);
        cp16(base + 2 * GARR_B + 80,   gBl + kc + 40);
        CP_COMMIT();
    };

    load_stage(0, 0);
    load_stage(1, 1);

    for (int c = 0; c < NCH; ++c) {
        if (c == NCH - 1) { CP_WAIT0(); } else { CP_WAIT1(); }
        __syncthreads();

        const int st = c & 1;
        const uint32_t bAh = sb + st * GSTG_B;
        const uint32_t bBh = bAh + GARR_B;
        const uint32_t bBl = bAh + 2 * GARR_B;

        #pragma unroll
        for (int ks = 0; ks < 4; ++ks) {
            const int kb = ks * 32;
            uint32_t a[4][4], bh[4][2], bl[4][2];
            #pragma unroll
            for (int mi = 0; mi < 4; ++mi) {
                const int mo = mi * 16 * SAST * 2 + kb;
                ldsm4(bAh + aoff + mo, a[mi][0], a[mi][1], a[mi][2], a[mi][3]);
            }
            #pragma unroll
            for (int nj = 0; nj < 2; ++nj) {
                const int no = nj * 16 * SAST * 2 + kb;
                uint32_t t0, t1, t2, t3;
                ldsm4(bBh + boff + no, t0, t1, t2, t3);
                bh[nj * 2][0] = t0; bh[nj * 2][1] = t1;
                bh[nj * 2 + 1][0] = t2; bh[nj * 2 + 1][1] = t3;
                ldsm4(bBl + boff + no, t0, t1, t2, t3);
                bl[nj * 2][0] = t0; bl[nj * 2][1] = t1;
                bl[nj * 2 + 1][0] = t2; bl[nj * 2 + 1][1] = t3;
            }
            #pragma unroll
            for (int mi = 0; mi < 4; ++mi)
                #pragma unroll
                for (int ni = 0; ni < 4; ++ni) {
                    mma16816(acc[mi][ni], a[mi], bh[ni]);
                    mma16816h(accl[mi][ni], a[mi], bl[ni]);
                }
        }
        __syncthreads();
        if (c + 2 < NCH) load_stage(c + 2, st);
    }

    const int rbase = m0 + wm + (lane >> 2);
    const int cbase = n0 + wn + (lane & 3) * 2;
    #pragma unroll
    for (int mi = 0; mi < 4; ++mi) {
        const int r = rbase + mi * 16;
        #pragma unroll
        for (int ni = 0; ni < 4; ++ni) {
            const int c = cbase + ni * 8;
            const __half2 l01 = *reinterpret_cast<const __half2*>(&accl[mi][ni][0]);
            const __half2 l23 = *reinterpret_cast<const __half2*>(&accl[mi][ni][1]);
            const float b0 = bias[c], b1 = bias[c + 1];
            const float v0 = acc[mi][ni][0] + LO_UNSCALE * __low2float(l01)  + b0;
            const float v1 = acc[mi][ni][1] + LO_UNSCALE * __high2float(l01) + b1;
            const float v2 = acc[mi][ni][2] + LO_UNSCALE * __low2float(l23)  + b0;
            const float v3 = acc[mi][ni][3] + LO_UNSCALE * __high2float(l23) + b1;
            if (HALF_OUT) {
                *(uint32_t*)&Ch[(size_t)r * N + c]       = pack_h(v0, v1);
                *(uint32_t*)&Ch[(size_t)(r + 8) * N + c] = pack_h(v2, v3);
            } else {
                float2 o0 = { v0, v1 }, o1 = { v2, v3 };
                *(float2*)&Cf[(size_t)r * N + c] = o0;
                *(float2*)&Cf[(size_t)(r + 8) * N + c] = o1;
            }
        }
    }
}

// ---------------------------------------------------------------------------
// fp16 flash attention (causal, no-transpose head reshape), single-precision
// K/V (no lo terms): S = Qh·Kh, O = Ph·Vh.  qt reversed for tail packing.
// ---------------------------------------------------------------------------
#define FST 72
#define FLASH_SMEM (3 * 64 * FST * 2)

__global__ __launch_bounds__(128) void flash_mma(
    const __half* __restrict__ qkvh, __half* __restrict__ attn)
{
    extern __shared__ __half fsm[];
    __half* sQ = fsm;
    __half* sK = fsm + 1 * 64 * FST;
    __half* sV = fsm + 2 * 64 * FST;

    const int b = blockIdx.z, h = blockIdx.y;
    const int qt = gridDim.x - 1 - blockIdx.x;
    const int tid = threadIdx.x, lane = tid & 31, wid = tid >> 5;
    const size_t bbase = (size_t)b * SEQ * 3 * EMB;
    const int hbase = h * SEQ * HD;
    const int q0 = qt * 64;

    #pragma unroll
    for (int i = 0; i < 4; ++i) {
        const int id = tid + 128 * i;
        const int r = id >> 3, c = (id & 7) * 8;
        const int f = hbase + (q0 + r) * HD + c;
        const size_t ga = bbase + (size_t)(f >> 10) * 3072 + (f & 1023);
        *(uint4*)&sQ[r * FST + c] = *(const uint4*)&qkvh[ga];
    }
    __syncthreads();

    const uint32_t bQ = (uint32_t)__cvta_generic_to_shared(sQ);
    const uint32_t bK = (uint32_t)__cvta_generic_to_shared(sK);
    const uint32_t bV = (uint32_t)__cvta_generic_to_shared(sV);

    const int aoff = ((wid * 16 + (lane & 15)) * FST + (lane >> 4) * 8) * 2;
    uint32_t qf[4][4];
    #pragma unroll
    for (int kt = 0; kt < 4; ++kt)
        ldsm4(bQ + aoff + kt * 32, qf[kt][0], qf[kt][1], qf[kt][2], qf[kt][3]);

    const int boffK = (((lane & 7) + ((lane >> 4) & 1) * 8) * FST + ((lane >> 3) & 1) * 8) * 2;
    const int voffV = (((lane & 7) + ((lane >> 3) & 1) * 8) * FST + (lane >> 4) * 8) * 2;

    float m_r[2] = { -INFINITY, -INFINITY };
    float l_r[2] = { 0.f, 0.f };
    float oacc[8][4];
    #pragma unroll
    for (int nt = 0; nt < 8; ++nt)
        oacc[nt][0] = oacc[nt][1] = oacc[nt][2] = oacc[nt][3] = 0.f;

    const int rloc = wid * 16 + (lane >> 2);
    const int cloc = 2 * (lane & 3);

    for (int j0 = 0; j0 <= qt; ++j0) {
        __syncthreads();
        #pragma unroll
        for (int i = 0; i < 4; ++i) {
            const int id = tid + 128 * i;
            const int r = id >> 3, c = (id & 7) * 8;
            const int f = hbase + (j0 * 64 + r) * HD + c;
            const size_t ga = bbase + (size_t)(f >> 10) * 3072 + (f & 1023);
            *(uint4*)&sK[r * FST + c] = *(const uint4*)&qkvh[ga + 1024];
            *(uint4*)&sV[r * FST + c] = *(const uint4*)&qkvh[ga + 2048];
        }
        __syncthreads();

        float sacc[8][4];
        #pragma unroll
        for (int nt = 0; nt < 8; ++nt)
            sacc[nt][0] = sacc[nt][1] = sacc[nt][2] = sacc[nt][3] = 0.f;

        #pragma unroll
        for (int kt = 0; kt < 4; ++kt) {
            #pragma unroll
            for (int nj = 0; nj < 4; ++nj) {
                uint32_t h0, h1, h2, h3;
                const int off = nj * 16 * FST * 2 + kt * 32;
                ldsm4(bK + boffK + off, h0, h1, h2, h3);
                uint32_t bh0[2] = { h0, h1 }, bh1[2] = { h2, h3 };
                mma16816(sacc[nj * 2], qf[kt], bh0);
                mma16816(sacc[nj * 2 + 1], qf[kt], bh1);
            }
        }

        #pragma unroll
        for (int nt = 0; nt < 8; ++nt) {
            sacc[nt][0] *= 0.125f; sacc[nt][1] *= 0.125f;
            sacc[nt][2] *= 0.125f; sacc[nt][3] *= 0.125f;
        }
        if (j0 == qt) {
            #pragma unroll
            for (int nt = 0; nt < 8; ++nt) {
                const int jc = nt * 8 + cloc;
                if (jc > rloc)     sacc[nt][0] = -INFINITY;
                if (jc + 1 > rloc) sacc[nt][1] = -INFINITY;
                if (jc > rloc + 8)     sacc[nt][2] = -INFINITY;
                if (jc + 1 > rloc + 8) sacc[nt][3] = -INFINITY;
            }
        }
        float mx0 = -INFINITY, mx1 = -INFINITY;
        #pragma unroll
        for (int nt = 0; nt < 8; ++nt) {
            mx0 = fmaxf(mx0, fmaxf(sacc[nt][0], sacc[nt][1]));
            mx1 = fmaxf(mx1, fmaxf(sacc[nt][2], sacc[nt][3]));
        }
        mx0 = fmaxf(mx0, __shfl_xor_sync(0xffffffffu, mx0, 1));
        mx0 = fmaxf(mx0, __shfl_xor_sync(0xffffffffu, mx0, 2));
        mx1 = fmaxf(mx1, __shfl_xor_sync(0xffffffffu, mx1, 1));
        mx1 = fmaxf(mx1, __shfl_xor_sync(0xffffffffu, mx1, 2));
        const float mn0 = fmaxf(m_r[0], mx0), mn1 = fmaxf(m_r[1], mx1);
        const float al0 = __expf(m_r[0] - mn0), al1 = __expf(m_r[1] - mn1);
        m_r[0] = mn0; m_r[1] = mn1;

        float rs0 = 0.f, rs1 = 0.f;
        #pragma unroll
        for (int nt = 0; nt < 8; ++nt) {
            sacc[nt][0] = __expf(sacc[nt][0] - mn0); rs0 += sacc[nt][0];
            sacc[nt][1] = __expf(sacc[nt][1] - mn0); rs0 += sacc[nt][1];
            sacc[nt][2] = __expf(sacc[nt][2] - mn1); rs1 += sacc[nt][2];
            sacc[nt][3] = __expf(sacc[nt][3] - mn1); rs1 += sacc[nt][3];
        }
        rs0 += __shfl_xor_sync(0xffffffffu, rs0, 1);
        rs0 += __shfl_xor_sync(0xffffffffu, rs0, 2);
        rs1 += __shfl_xor_sync(0xffffffffu, rs1, 1);
        rs1 += __shfl_xor_sync(0xffffffffu, rs1, 2);
        l_r[0] = l_r[0] * al0 + rs0;
        l_r[1] = l_r[1] * al1 + rs1;
        #pragma unroll
        for (int nt = 0; nt < 8; ++nt) {
            oacc[nt][0] *= al0; oacc[nt][1] *= al0;
            oacc[nt][2] *= al1; oacc[nt][3] *= al1;
        }

        #pragma unroll
        for (int kt = 0; kt < 4; ++kt) {
            uint32_t ph[4];
            ph[0] = pack_h(sacc[2 * kt][0], sacc[2 * kt][1]);
            ph[1] = pack_h(sacc[2 * kt][2], sacc[2 * kt][3]);
            ph[2] = pack_h(sacc[2 * kt + 1][0], sacc[2 * kt + 1][1]);
            ph[3] = pack_h(sacc[2 * kt + 1][2], sacc[2 * kt + 1][3]);
            #pragma unroll
            for (int nj = 0; nj < 4; ++nj) {
                uint32_t v0, v1, v2, v3;
                const int off = kt * 16 * FST * 2 + nj * 32;
                ldsm4t(bV + voffV + off, v0, v1, v2, v3);
                uint32_t vh0[2] = { v0, v1 }, vh1[2] = { v2, v3 };
                mma16816(oacc[nj * 2], ph, vh0);
                mma16816(oacc[nj * 2 + 1], ph, vh1);
            }
        }
    }

    const float inv0 = 1.f / l_r[0], inv1 = 1.f / l_r[1];
    const int qrow = q0 + rloc;
    #pragma unroll
    for (int nt = 0; nt < 8; ++nt) {
        const int col = h * HD + nt * 8 + cloc;
        const float v0 = oacc[nt][0] * inv0, v1 = oacc[nt][1] * inv0;
        const float v2 = oacc[nt][2] * inv1, v3 = oacc[nt][3] * inv1;
        const size_t r0 = ((size_t)b * SEQ + qrow) * EMB + col;
        const size_t r1 = ((size_t)b * SEQ + qrow + 8) * EMB + col;
        *(uint32_t*)&attn[r0] = pack_h(v0, v1);
        *(uint32_t*)&attn[r1] = pack_h(v2, v3);
    }
}

// ---------------------------------------------------------------------------
extern "C" void kernel_launch(void* const* d_in, const int* in_sizes, int n_in,
                              void* d_out, int out_size)
{
    const float* x    = (const float*)d_in[0];
    const float* Wqkv = (const float*)d_in[1];
    const float* bqkv = (const float*)d_in[2];
    const float* Wout = (const float*)d_in[3];
    const float* bout = (const float*)d_in[4];
    float* out = (float*)d_out;

    __half *xh, *w1h, *w1l, *w2h, *w2l, *qkvh, *ah;
    cudaGetSymbolAddress((void**)&xh, g_xh);
    cudaGetSymbolAddress((void**)&w1h, g_w1h);
    cudaGetSymbolAddress((void**)&w1l, g_w1l);
    cudaGetSymbolAddress((void**)&w2h, g_w2h);
    cudaGetSymbolAddress((void**)&w2l, g_w2l);
    cudaGetSymbolAddress((void**)&qkvh, g_qkvh);
    cudaGetSymbolAddress((void**)&ah, g_ah);

    cudaFuncSetAttribute(flash_mma,
                         cudaFuncAttributeMaxDynamicSharedMemorySize, FLASH_SMEM);
    cudaFuncSetAttribute(mma_gemm_bias<true>,
                         cudaFuncAttributeMaxDynamicSharedMemorySize, GEMM_SMEM);
    cudaFuncSetAttribute(mma_gemm_bias<false>,
                         cudaFuncAttributeMaxDynamicSharedMemorySize, GEMM_SMEM);

    const int nx  = BSZ * SEQ * EMB;
    const int nw1 = 3 * EMB * EMB;
    const int nw2 = EMB * EMB;

    // 0) conversions
    conv_kernel<<<nx / 4 / 256, 256>>>((const float4*)x, (uint2*)xh, nx / 4);
    split_kernel<<<nw1 / 4 / 256, 256>>>((const float4*)Wqkv, (uint2*)w1h, (uint2*)w1l, nw1 / 4);
    split_kernel<<<nw2 / 4 / 256, 256>>>((const float4*)Wout, (uint2*)w2h, (uint2*)w2l, nw2 / 4);

    // 1) qkv = x @ Wqkv^T + bqkv  -> fp16
    mma_gemm_bias<true><<<dim3(3 * EMB / 128, BSZ * SEQ / 128), 256, GEMM_SMEM>>>(
        xh, w1h, w1l, bqkv, nullptr, qkvh, BSZ * SEQ, 3 * EMB, EMB);

    // 2) causal flash attention -> attn fp16
    flash_mma<<<dim3(SEQ / 64, NH, BSZ), 128, FLASH_SMEM>>>(qkvh, ah);

    // 3) out = attn @ Wout^T + bout  (fp32 out)
    mma_gemm_bias<false><<<dim3(EMB / 128, BSZ * SEQ / 128), 256, GEMM_SMEM>>>(
        ah, w2h, w2l, bout, out, nullptr, BSZ * SEQ, EMB, EMB);
}

// round 9
// speedup vs baseline: 5.8858x; 1.5109x over previous
#include <cuda_runtime.h>
#include <cuda_fp16.h>
#include <math.h>
#include <stdint.h>

#define BSZ 2
#define SEQ 2048
#define EMB 1024
#define NH  16
#define HD  64

// ---------------------------------------------------------------------------
// Scratch (__device__ globals)
// ---------------------------------------------------------------------------
__device__ __half g_xh[(size_t)BSZ * SEQ * EMB];
__device__ __half g_w1h[(size_t)3 * EMB * EMB];
__device__ __half g_w2h[(size_t)EMB * EMB];
__device__ __half g_qkvh[(size_t)BSZ * SEQ * 3 * EMB];
__device__ __half g_ah[(size_t)BSZ * SEQ * EMB];

// ---------------------------------------------------------------------------
// fp32 -> fp16 convert
// ---------------------------------------------------------------------------
__global__ __launch_bounds__(256) void conv_kernel(
    const float4* __restrict__ in, uint2* __restrict__ hi, int n4)
{
    int i = blockIdx.x * blockDim.x + threadIdx.x;
    if (i >= n4) return;
    float4 v = in[i];
    __half2 a(__float2half_rn(v.x), __float2half_rn(v.y));
    __half2 b(__float2half_rn(v.z), __float2half_rn(v.w));
    uint2 H;
    H.x = *reinterpret_cast<uint32_t*>(&a);
    H.y = *reinterpret_cast<uint32_t*>(&b);
    hi[i] = H;
}

// ---------------------------------------------------------------------------
// MMA / cp.async helpers
// ---------------------------------------------------------------------------
__device__ __forceinline__ void ldsm4(uint32_t a, uint32_t& r0, uint32_t& r1,
                                      uint32_t& r2, uint32_t& r3)
{
    asm volatile("ldmatrix.sync.aligned.m8n8.x4.shared.b16 {%0,%1,%2,%3}, [%4];\n"
                 : "=r"(r0), "=r"(r1), "=r"(r2), "=r"(r3) : "r"(a));
}
__device__ __forceinline__ void ldsm4t(uint32_t a, uint32_t& r0, uint32_t& r1,
                                       uint32_t& r2, uint32_t& r3)
{
    asm volatile("ldmatrix.sync.aligned.m8n8.x4.trans.shared.b16 {%0,%1,%2,%3}, [%4];\n"
                 : "=r"(r0), "=r"(r1), "=r"(r2), "=r"(r3) : "r"(a));
}
__device__ __forceinline__ void mma16816(float* d, const uint32_t* a, const uint32_t* b)
{
    asm volatile("mma.sync.aligned.m16n8k16.row.col.f32.f16.f16.f32 "
                 "{%0,%1,%2,%3}, {%4,%5,%6,%7}, {%8,%9}, {%0,%1,%2,%3};\n"
                 : "+f"(d[0]), "+f"(d[1]), "+f"(d[2]), "+f"(d[3])
                 : "r"(a[0]), "r"(a[1]), "r"(a[2]), "r"(a[3]), "r"(b[0]), "r"(b[1]));
}
__device__ __forceinline__ uint32_t pack_h(float a, float b)
{
    __half2 p(__float2half_rn(a), __float2half_rn(b));
    return *reinterpret_cast<uint32_t*>(&p);
}
__device__ __forceinline__ void cp16(uint32_t saddr, const void* gaddr)
{
    asm volatile("cp.async.cg.shared.global [%0], [%1], 16;" :: "r"(saddr), "l"(gaddr));
}
#define CP_COMMIT() asm volatile("cp.async.commit_group;" ::: "memory")
#define CP_WAIT1()  asm volatile("cp.async.wait_group 1;" ::: "memory")
#define CP_WAIT0()  asm volatile("cp.async.wait_group 0;" ::: "memory")

// ---------------------------------------------------------------------------
// Pure fp16 GEMM:  C = A·B^T + bias   (single MMA term, fp32 accumulate)
// CTA 128x128, warp 64x32, K-chunks of 64 via 2-stage cp.async, 2 CTAs/SM.
// ---------------------------------------------------------------------------
#define SAST 72
#define GARR_B  (128 * SAST * 2)        // 18432 B per array
#define GSTG_B  (2 * GARR_B)            // 36864 B per stage (A, B)
#define GEMM_SMEM (2 * GSTG_B)          // 73728

template<bool HALF_OUT>
__global__ __launch_bounds__(256, 2) void mma_gemm_bias(
    const __half* __restrict__ Ah, const __half* __restrict__ Bh,
    const float* __restrict__ bias, float* __restrict__ Cf,
    __half* __restrict__ Ch,
    int M, int N, int K)
{
    extern __shared__ __align__(16) unsigned char gsm[];
    const uint32_t sb = (uint32_t)__cvta_generic_to_shared(gsm);

    const int tid = threadIdx.x, lane = tid & 31, wid = tid >> 5;
    const int wm = (wid >> 2) * 64;
    const int wn = (wid & 3) * 32;
    const int m0 = blockIdx.y * 128, n0 = blockIdx.x * 128;

    const int lrow = tid >> 1;
    const int lcol = (tid & 1) * 16;
    const uint32_t so = (uint32_t)(lrow * SAST + lcol) * 2;
    const __half* gA = Ah + (size_t)(m0 + lrow) * K + lcol;
    const __half* gB = Bh + (size_t)(n0 + lrow) * K + lcol;

    const int aoff = ((wm + (lane & 15)) * SAST + (lane >> 4) * 8) * 2;
    const int boff = ((wn + (lane & 7) + ((lane >> 4) & 1) * 8) * SAST
                      + ((lane >> 3) & 1) * 8) * 2;

    float acc[4][4][4];
    #pragma unroll
    for (int i = 0; i < 4; ++i)
        #pragma unroll
        for (int j = 0; j < 4; ++j)
            acc[i][j][0] = acc[i][j][1] = acc[i][j][2] = acc[i][j][3] = 0.f;

    const int NCH = K / 64;

    auto load_stage = [&](int c, int st) {
        const int kc = c * 64;
        const uint32_t base = sb + st * GSTG_B + so;
        cp16(base,                gA + kc);
        cp16(base + 16,           gA + kc + 8);
        cp16(base + 64,           gA + kc + 32);
        cp16(base + 80,           gA + kc + 40);
        cp16(base + GARR_B,       gB + kc);
        cp16(base + GARR_B + 16,  gB + kc + 8);
        cp16(base + GARR_B + 64,  gB + kc + 32);
        cp16(base + GARR_B + 80,  gB + kc + 40);
        CP_COMMIT();
    };

    load_stage(0, 0);
    load_stage(1, 1);

    for (int c = 0; c < NCH; ++c) {
        if (c == NCH - 1) { CP_WAIT0(); } else { CP_WAIT1(); }
        __syncthreads();

        const int st = c & 1;
        const uint32_t bA = sb + st * GSTG_B;
        const uint32_t bB = bA + GARR_B;

        #pragma unroll
        for (int ks = 0; ks < 4; ++ks) {
            const int kb = ks * 32;
            uint32_t a[4][4], bfr[4][2];
            #pragma unroll
            for (int mi = 0; mi < 4; ++mi) {
                const int mo = mi * 16 * SAST * 2 + kb;
                ldsm4(bA + aoff + mo, a[mi][0], a[mi][1], a[mi][2], a[mi][3]);
            }
            #pragma unroll
            for (int nj = 0; nj < 2; ++nj) {
                const int no = nj * 16 * SAST * 2 + kb;
                uint32_t t0, t1, t2, t3;
                ldsm4(bB + boff + no, t0, t1, t2, t3);
                bfr[nj * 2][0] = t0; bfr[nj * 2][1] = t1;
                bfr[nj * 2 + 1][0] = t2; bfr[nj * 2 + 1][1] = t3;
            }
            #pragma unroll
            for (int mi = 0; mi < 4; ++mi)
                #pragma unroll
                for (int ni = 0; ni < 4; ++ni)
                    mma16816(acc[mi][ni], a[mi], bfr[ni]);
        }
        __syncthreads();
        if (c + 2 < NCH) load_stage(c + 2, st);
    }

    const int rbase = m0 + wm + (lane >> 2);
    const int cbase = n0 + wn + (lane & 3) * 2;
    #pragma unroll
    for (int mi = 0; mi < 4; ++mi) {
        const int r = rbase + mi * 16;
        #pragma unroll
        for (int ni = 0; ni < 4; ++ni) {
            const int c = cbase + ni * 8;
            const float b0 = bias[c], b1 = bias[c + 1];
            const float v0 = acc[mi][ni][0] + b0, v1 = acc[mi][ni][1] + b1;
            const float v2 = acc[mi][ni][2] + b0, v3 = acc[mi][ni][3] + b1;
            if (HALF_OUT) {
                *(uint32_t*)&Ch[(size_t)r * N + c]       = pack_h(v0, v1);
                *(uint32_t*)&Ch[(size_t)(r + 8) * N + c] = pack_h(v2, v3);
            } else {
                float2 o0 = { v0, v1 }, o1 = { v2, v3 };
                *(float2*)&Cf[(size_t)r * N + c] = o0;
                *(float2*)&Cf[(size_t)(r + 8) * N + c] = o1;
            }
        }
    }
}

// ---------------------------------------------------------------------------
// fp16 flash attention (causal, no-transpose head reshape), unchanged from R8.
// ---------------------------------------------------------------------------
#define FST 72
#define FLASH_SMEM (3 * 64 * FST * 2)

__global__ __launch_bounds__(128) void flash_mma(
    const __half* __restrict__ qkvh, __half* __restrict__ attn)
{
    extern __shared__ __half fsm[];
    __half* sQ = fsm;
    __half* sK = fsm + 1 * 64 * FST;
    __half* sV = fsm + 2 * 64 * FST;

    const int b = blockIdx.z, h = blockIdx.y;
    const int qt = gridDim.x - 1 - blockIdx.x;
    const int tid = threadIdx.x, lane = tid & 31, wid = tid >> 5;
    const size_t bbase = (size_t)b * SEQ * 3 * EMB;
    const int hbase = h * SEQ * HD;
    const int q0 = qt * 64;

    #pragma unroll
    for (int i = 0; i < 4; ++i) {
        const int id = tid + 128 * i;
        const int r = id >> 3, c = (id & 7) * 8;
        const int f = hbase + (q0 + r) * HD + c;
        const size_t ga = bbase + (size_t)(f >> 10) * 3072 + (f & 1023);
        *(uint4*)&sQ[r * FST + c] = *(const uint4*)&qkvh[ga];
    }
    __syncthreads();

    const uint32_t bQ = (uint32_t)__cvta_generic_to_shared(sQ);
    const uint32_t bK = (uint32_t)__cvta_generic_to_shared(sK);
    const uint32_t bV = (uint32_t)__cvta_generic_to_shared(sV);

    const int aoff = ((wid * 16 + (lane & 15)) * FST + (lane >> 4) * 8) * 2;
    uint32_t qf[4][4];
    #pragma unroll
    for (int kt = 0; kt < 4; ++kt)
        ldsm4(bQ + aoff + kt * 32, qf[kt][0], qf[kt][1], qf[kt][2], qf[kt][3]);

    const int boffK = (((lane & 7) + ((lane >> 4) & 1) * 8) * FST + ((lane >> 3) & 1) * 8) * 2;
    const int voffV = (((lane & 7) + ((lane >> 3) & 1) * 8) * FST + (lane >> 4) * 8) * 2;

    float m_r[2] = { -INFINITY, -INFINITY };
    float l_r[2] = { 0.f, 0.f };
    float oacc[8][4];
    #pragma unroll
    for (int nt = 0; nt < 8; ++nt)
        oacc[nt][0] = oacc[nt][1] = oacc[nt][2] = oacc[nt][3] = 0.f;

    const int rloc = wid * 16 + (lane >> 2);
    const int cloc = 2 * (lane & 3);

    for (int j0 = 0; j0 <= qt; ++j0) {
        __syncthreads();
        #pragma unroll
        for (int i = 0; i < 4; ++i) {
            const int id = tid + 128 * i;
            const int r = id >> 3, c = (id & 7) * 8;
            const int f = hbase + (j0 * 64 + r) * HD + c;
            const size_t ga = bbase + (size_t)(f >> 10) * 3072 + (f & 1023);
            *(uint4*)&sK[r * FST + c] = *(const uint4*)&qkvh[ga + 1024];
            *(uint4*)&sV[r * FST + c] = *(const uint4*)&qkvh[ga + 2048];
        }
        __syncthreads();

        float sacc[8][4];
        #pragma unroll
        for (int nt = 0; nt < 8; ++nt)
            sacc[nt][0] = sacc[nt][1] = sacc[nt][2] = sacc[nt][3] = 0.f;

        #pragma unroll
        for (int kt = 0; kt < 4; ++kt) {
            #pragma unroll
            for (int nj = 0; nj < 4; ++nj) {
                uint32_t h0, h1, h2, h3;
                const int off = nj * 16 * FST * 2 + kt * 32;
                ldsm4(bK + boffK + off, h0, h1, h2, h3);
                uint32_t bh0[2] = { h0, h1 }, bh1[2] = { h2, h3 };
                mma16816(sacc[nj * 2], qf[kt], bh0);
                mma16816(sacc[nj * 2 + 1], qf[kt], bh1);
            }
        }

        #pragma unroll
        for (int nt = 0; nt < 8; ++nt) {
            sacc[nt][0] *= 0.125f; sacc[nt][1] *= 0.125f;
            sacc[nt][2] *= 0.125f; sacc[nt][3] *= 0.125f;
        }
        if (j0 == qt) {
            #pragma unroll
            for (int nt = 0; nt < 8; ++nt) {
                const int jc = nt * 8 + cloc;
                if (jc > rloc)     sacc[nt][0] = -INFINITY;
                if (jc + 1 > rloc) sacc[nt][1] = -INFINITY;
                if (jc > rloc + 8)     sacc[nt][2] = -INFINITY;
                if (jc + 1 > rloc + 8) sacc[nt][3] = -INFINITY;
            }
        }
        float mx0 = -INFINITY, mx1 = -INFINITY;
        #pragma unroll
        for (int nt = 0; nt < 8; ++nt) {
            mx0 = fmaxf(mx0, fmaxf(sacc[nt][0], sacc[nt][1]));
            mx1 = fmaxf(mx1, fmaxf(sacc[nt][2], sacc[nt][3]));
        }
        mx0 = fmaxf(mx0, __shfl_xor_sync(0xffffffffu, mx0, 1));
        mx0 = fmaxf(mx0, __shfl_xor_sync(0xffffffffu, mx0, 2));
        mx1 = fmaxf(mx1, __shfl_xor_sync(0xffffffffu, mx1, 1));
        mx1 = fmaxf(mx1, __shfl_xor_sync(0xffffffffu, mx1, 2));
        const float mn0 = fmaxf(m_r[0], mx0), mn1 = fmaxf(m_r[1], mx1);
        const float al0 = __expf(m_r[0] - mn0), al1 = __expf(m_r[1] - mn1);
        m_r[0] = mn0; m_r[1] = mn1;

        float rs0 = 0.f, rs1 = 0.f;
        #pragma unroll
        for (int nt = 0; nt < 8; ++nt) {
            sacc[nt][0] = __expf(sacc[nt][0] - mn0); rs0 += sacc[nt][0];
            sacc[nt][1] = __expf(sacc[nt][1] - mn0); rs0 += sacc[nt][1];
            sacc[nt][2] = __expf(sacc[nt][2] - mn1); rs1 += sacc[nt][2];
            sacc[nt][3] = __expf(sacc[nt][3] - mn1); rs1 += sacc[nt][3];
        }
        rs0 += __shfl_xor_sync(0xffffffffu, rs0, 1);
        rs0 += __shfl_xor_sync(0xffffffffu, rs0, 2);
        rs1 += __shfl_xor_sync(0xffffffffu, rs1, 1);
        rs1 += __shfl_xor_sync(0xffffffffu, rs1, 2);
        l_r[0] = l_r[0] * al0 + rs0;
        l_r[1] = l_r[1] * al1 + rs1;
        #pragma unroll
        for (int nt = 0; nt < 8; ++nt) {
            oacc[nt][0] *= al0; oacc[nt][1] *= al0;
            oacc[nt][2] *= al1; oacc[nt][3] *= al1;
        }

        #pragma unroll
        for (int kt = 0; kt < 4; ++kt) {
            uint32_t ph[4];
            ph[0] = pack_h(sacc[2 * kt][0], sacc[2 * kt][1]);
            ph[1] = pack_h(sacc[2 * kt][2], sacc[2 * kt][3]);
            ph[2] = pack_h(sacc[2 * kt + 1][0], sacc[2 * kt + 1][1]);
            ph[3] = pack_h(sacc[2 * kt + 1][2], sacc[2 * kt + 1][3]);
            #pragma unroll
            for (int nj = 0; nj < 4; ++nj) {
                uint32_t v0, v1, v2, v3;
                const int off = kt * 16 * FST * 2 + nj * 32;
                ldsm4t(bV + voffV + off, v0, v1, v2, v3);
                uint32_t vh0[2] = { v0, v1 }, vh1[2] = { v2, v3 };
                mma16816(oacc[nj * 2], ph, vh0);
                mma16816(oacc[nj * 2 + 1], ph, vh1);
            }
        }
    }

    const float inv0 = 1.f / l_r[0], inv1 = 1.f / l_r[1];
    const int qrow = q0 + rloc;
    #pragma unroll
    for (int nt = 0; nt < 8; ++nt) {
        const int col = h * HD + nt * 8 + cloc;
        const float v0 = oacc[nt][0] * inv0, v1 = oacc[nt][1] * inv0;
        const float v2 = oacc[nt][2] * inv1, v3 = oacc[nt][3] * inv1;
        const size_t r0 = ((size_t)b * SEQ + qrow) * EMB + col;
        const size_t r1 = ((size_t)b * SEQ + qrow + 8) * EMB + col;
        *(uint32_t*)&attn[r0] = pack_h(v0, v1);
        *(uint32_t*)&attn[r1] = pack_h(v2, v3);
    }
}

// ---------------------------------------------------------------------------
extern "C" void kernel_launch(void* const* d_in, const int* in_sizes, int n_in,
                              void* d_out, int out_size)
{
    const float* x    = (const float*)d_in[0];
    const float* Wqkv = (const float*)d_in[1];
    const float* bqkv = (const float*)d_in[2];
    const float* Wout = (const float*)d_in[3];
    const float* bout = (const float*)d_in[4];
    float* out = (float*)d_out;

    __half *xh, *w1h, *w2h, *qkvh, *ah;
    cudaGetSymbolAddress((void**)&xh, g_xh);
    cudaGetSymbolAddress((void**)&w1h, g_w1h);
    cudaGetSymbolAddress((void**)&w2h, g_w2h);
    cudaGetSymbolAddress((void**)&qkvh, g_qkvh);
    cudaGetSymbolAddress((void**)&ah, g_ah);

    cudaFuncSetAttribute(flash_mma,
                         cudaFuncAttributeMaxDynamicSharedMemorySize, FLASH_SMEM);
    cudaFuncSetAttribute(mma_gemm_bias<true>,
                         cudaFuncAttributeMaxDynamicSharedMemorySize, GEMM_SMEM);
    cudaFuncSetAttribute(mma_gemm_bias<false>,
                         cudaFuncAttributeMaxDynamicSharedMemorySize, GEMM_SMEM);

    const int nx  = BSZ * SEQ * EMB;
    const int nw1 = 3 * EMB * EMB;
    const int nw2 = EMB * EMB;

    // 0) fp32 -> fp16 conversions
    conv_kernel<<<nx / 4 / 256, 256>>>((const float4*)x, (uint2*)xh, nx / 4);
    conv_kernel<<<nw1 / 4 / 256, 256>>>((const float4*)Wqkv, (uint2*)w1h, nw1 / 4);
    conv_kernel<<<nw2 / 4 / 256, 256>>>((const float4*)Wout, (uint2*)w2h, nw2 / 4);

    // 1) qkv = x @ Wqkv^T + bqkv  -> fp16
    mma_gemm_bias<true><<<dim3(3 * EMB / 128, BSZ * SEQ / 128), 256, GEMM_SMEM>>>(
        xh, w1h, bqkv, nullptr, qkvh, BSZ * SEQ, 3 * EMB, EMB);

    // 2) causal flash attention -> attn fp16
    flash_mma<<<dim3(SEQ / 64, NH, BSZ), 128, FLASH_SMEM>>>(qkvh, ah);

    // 3) out = attn @ Wout^T + bout  (fp32 out)
    mma_gemm_bias<false><<<dim3(EMB / 128, BSZ * SEQ / 128), 256, GEMM_SMEM>>>(
        ah, w2h, bout, out, nullptr, BSZ * SEQ, EMB, EMB);
}